// round 2
// baseline (speedup 1.0000x reference)
#include <cuda_runtime.h>
#include <math.h>

// ---------------- problem constants (fixed by reference) ----------------
#define Dm 256          // d_model
#define Hh 8            // heads
#define HD 32           // head dim
#define NQMAX 128       // >= NQ (=100)
#define MAXB 16
#define MAX_TOTAL 65536
#define SPLIT_LEN 2048
#define MAX_SPLITS 32   // covers one batch owning all MAX_TOTAL tokens

// ---------------- device scratch (no runtime allocation allowed) --------
__device__ float g_K[MAX_TOTAL * Dm];                       // 64 MB
__device__ float g_V[MAX_TOTAL * Dm];                       // 64 MB
__device__ float g_Q[MAXB * NQMAX * Dm];                    // scaled q proj
__device__ float g_ctx[MAXB * NQMAX * Dm];                  // attention context
__device__ float g_ctx_part[(size_t)MAXB * Hh * MAX_SPLITS * NQMAX * HD];
__device__ float g_m_part[(size_t)MAXB * Hh * MAX_SPLITS * NQMAX];
__device__ float g_l_part[(size_t)MAXB * Hh * MAX_SPLITS * NQMAX];

// ---------------- generic tiled SGEMM: out = alpha*(A @ W^T + bias) + resid
// A: (M,K) row-major. W: (N,K) row-major (torch Linear weight). out: (M,N).
#define BM 128
#define BN 64
#define BK 32

__global__ __launch_bounds__(256)
void sgemm_tn(const float* __restrict__ A, const float* __restrict__ W,
              const float* __restrict__ bias, const float* __restrict__ resid,
              float* __restrict__ out, int M, int N, int K, float alpha)
{
    __shared__ float As[BK][BM + 4];
    __shared__ float Ws[BK][BN + 4];

    const int t  = threadIdx.x;
    const int tx = t & 15;        // 16 col groups of 4
    const int ty = t >> 4;        // 16 row groups of 8
    const int m0 = blockIdx.x * BM;
    const int n0 = blockIdx.y * BN;

    float acc[8][4];
#pragma unroll
    for (int i = 0; i < 8; i++)
#pragma unroll
        for (int j = 0; j < 4; j++) acc[i][j] = 0.f;

    const int ar = t >> 3;            // 0..31
    const int ac = (t & 7) * 4;       // 0,4,...,28

    for (int k0 = 0; k0 < K; k0 += BK) {
        // stage A tile (BM x BK), transposed into As[k][m]
#pragma unroll
        for (int i = 0; i < 4; i++) {
            int row = ar + 32 * i;
            int gm  = m0 + row;
            float4 v = make_float4(0.f, 0.f, 0.f, 0.f);
            if (gm < M) v = *(const float4*)(A + (size_t)gm * K + k0 + ac);
            As[ac + 0][row] = v.x; As[ac + 1][row] = v.y;
            As[ac + 2][row] = v.z; As[ac + 3][row] = v.w;
        }
        // stage W tile (BN x BK), transposed into Ws[k][n]
#pragma unroll
        for (int i = 0; i < 2; i++) {
            int n = ar + 32 * i;
            float4 v = *(const float4*)(W + (size_t)(n0 + n) * K + k0 + ac);
            Ws[ac + 0][n] = v.x; Ws[ac + 1][n] = v.y;
            Ws[ac + 2][n] = v.z; Ws[ac + 3][n] = v.w;
        }
        __syncthreads();

#pragma unroll
        for (int kk = 0; kk < BK; kk++) {
            float a[8], w[4];
#pragma unroll
            for (int i = 0; i < 8; i++) a[i] = As[kk][ty * 8 + i];
#pragma unroll
            for (int j = 0; j < 4; j++) w[j] = Ws[kk][tx * 4 + j];
#pragma unroll
            for (int i = 0; i < 8; i++)
#pragma unroll
                for (int j = 0; j < 4; j++)
                    acc[i][j] = fmaf(a[i], w[j], acc[i][j]);
        }
        __syncthreads();
    }

#pragma unroll
    for (int i = 0; i < 8; i++) {
        int gm = m0 + ty * 8 + i;
        if (gm >= M) continue;
#pragma unroll
        for (int j = 0; j < 4; j++) {
            int gn = n0 + tx * 4 + j;
            float v = acc[i][j];
            if (bias) v += bias[gn];
            v *= alpha;
            if (resid) v += resid[(size_t)gm * N + gn];
            out[(size_t)gm * N + gn] = v;
        }
    }
}

// ---------------- split-K flash attention partials -----------------------
// One CTA per (batch, head, key-split). 128 threads, one query per thread.
#define TK 64

__global__ __launch_bounds__(128)
void attn_partial(const int* __restrict__ offs, int Bn, int NQn)
{
    const int s = blockIdx.x, h = blockIdx.y, b = blockIdx.z;
    const int tid = threadIdx.x;
    const int beg = offs[b];
    const int len = offs[b + 1] - beg;
    const int k0  = s * SPLIT_LEN;
    if (k0 >= len) return;                       // inactive split
    const int kend = min(k0 + SPLIT_LEN, len);

    __shared__ float Ks[TK][HD];
    __shared__ float Vs[TK][HD];

    float q[HD];
    if (tid < NQn) {
        const float* qp = g_Q + ((size_t)(b * NQn + tid)) * Dm + h * HD;
#pragma unroll
        for (int j = 0; j < HD; j++) q[j] = qp[j];
    }
    float m = -INFINITY, l = 0.f, acc[HD];
#pragma unroll
    for (int j = 0; j < HD; j++) acc[j] = 0.f;

    const int lr  = tid >> 3;           // 0..15
    const int lc4 = (tid & 7) * 4;      // 0..28

    for (int kt = k0; kt < kend; kt += TK) {
        const int nk = min(TK, kend - kt);
        // cooperative K/V tile load (float4, coalesced)
#pragma unroll
        for (int i = 0; i < 4; i++) {
            int row = lr + 16 * i;
            if (row < nk) {
                size_t gb = ((size_t)(beg + kt + row)) * Dm + h * HD + lc4;
                *(float4*)&Ks[row][lc4] = *(const float4*)(g_K + gb);
                *(float4*)&Vs[row][lc4] = *(const float4*)(g_V + gb);
            }
        }
        __syncthreads();

        if (tid < NQn) {
            for (int i = 0; i < nk; i++) {
                float sdot = 0.f;
#pragma unroll
                for (int j4 = 0; j4 < HD / 4; j4++) {
                    float4 kv = *(const float4*)&Ks[i][j4 * 4];
                    sdot = fmaf(q[j4 * 4 + 0], kv.x, sdot);
                    sdot = fmaf(q[j4 * 4 + 1], kv.y, sdot);
                    sdot = fmaf(q[j4 * 4 + 2], kv.z, sdot);
                    sdot = fmaf(q[j4 * 4 + 3], kv.w, sdot);
                }
                if (sdot > m) {                 // rare rescale path
                    float corr = __expf(m - sdot);
                    m = sdot;
                    l *= corr;
#pragma unroll
                    for (int j = 0; j < HD; j++) acc[j] *= corr;
                }
                float p = __expf(sdot - m);
                l += p;
#pragma unroll
                for (int j4 = 0; j4 < HD / 4; j4++) {
                    float4 vv = *(const float4*)&Vs[i][j4 * 4];
                    acc[j4 * 4 + 0] = fmaf(p, vv.x, acc[j4 * 4 + 0]);
                    acc[j4 * 4 + 1] = fmaf(p, vv.y, acc[j4 * 4 + 1]);
                    acc[j4 * 4 + 2] = fmaf(p, vv.z, acc[j4 * 4 + 2]);
                    acc[j4 * 4 + 3] = fmaf(p, vv.w, acc[j4 * 4 + 3]);
                }
            }
        }
        __syncthreads();
    }

    if (tid < NQn) {
        size_t pbase = ((size_t)(b * Hh + h) * MAX_SPLITS + s);
        g_m_part[pbase * NQMAX + tid] = m;
        g_l_part[pbase * NQMAX + tid] = l;
        float* cp = g_ctx_part + (pbase * NQMAX + tid) * HD;
#pragma unroll
        for (int j = 0; j < HD; j++) cp[j] = acc[j];
    }
}

// ---------------- combine split partials into g_ctx ----------------------
__global__ __launch_bounds__(128)
void attn_combine(const int* __restrict__ offs, int Bn, int NQn)
{
    int idx = blockIdx.x * blockDim.x + threadIdx.x;   // (b*H + h)*NQn + q
    int tot = Bn * Hh * NQn;
    if (idx >= tot) return;
    int q  = idx % NQn;
    int bh = idx / NQn;
    int b  = bh / Hh;
    int h  = bh % Hh;

    int len = offs[b + 1] - offs[b];
    int ns  = (len + SPLIT_LEN - 1) / SPLIT_LEN;
    if (ns < 1) ns = 1;
    if (ns > MAX_SPLITS) ns = MAX_SPLITS;

    size_t base = (size_t)bh * MAX_SPLITS;
    float M = -INFINITY;
    for (int s = 0; s < ns; s++)
        M = fmaxf(M, g_m_part[(base + s) * NQMAX + q]);

    float L = 0.f, ctx[HD];
#pragma unroll
    for (int j = 0; j < HD; j++) ctx[j] = 0.f;
    for (int s = 0; s < ns; s++) {
        float w = __expf(g_m_part[(base + s) * NQMAX + q] - M);
        L += w * g_l_part[(base + s) * NQMAX + q];
        const float* cp = g_ctx_part + ((base + s) * NQMAX + q) * HD;
#pragma unroll
        for (int j = 0; j < HD; j++) ctx[j] = fmaf(w, cp[j], ctx[j]);
    }
    float inv = 1.f / L;
    float* op = g_ctx + ((size_t)b * NQn + q) * Dm + h * HD;
#pragma unroll
    for (int j = 0; j < HD; j++) op[j] = ctx[j] * inv;
}

// ---------------- launch ---------------------------------------------------
extern "C" void kernel_launch(void* const* d_in, const int* in_sizes, int n_in,
                              void* d_out, int out_size)
{
    const float* source = (const float*)d_in[0];
    const float* query  = (const float*)d_in[1];
    const int*   offs   = (const int*)  d_in[2];
    const float* Wq = (const float*)d_in[3];  const float* bq = (const float*)d_in[4];
    const float* Wk = (const float*)d_in[5];  const float* bk = (const float*)d_in[6];
    const float* Wv = (const float*)d_in[7];  const float* bv = (const float*)d_in[8];
    const float* Wo = (const float*)d_in[9];  const float* bo = (const float*)d_in[10];
    float* out = (float*)d_out;

    const int total = in_sizes[0] / Dm;          // tokens
    const int Bn    = in_sizes[2] - 1;           // batch
    const int NQn   = in_sizes[1] / (Bn * Dm);   // queries per sample
    const int Mq    = Bn * NQn;                  // query rows
    const float scale = rsqrtf((float)HD);

    void *pK, *pV, *pQ, *pC;
    cudaGetSymbolAddress(&pK, g_K);
    cudaGetSymbolAddress(&pV, g_V);
    cudaGetSymbolAddress(&pQ, g_Q);
    cudaGetSymbolAddress(&pC, g_ctx);

    // 1) Q projection (scale folded in): g_Q = scale*(query @ Wq^T + bq)
    {
        dim3 grid((Mq + BM - 1) / BM, Dm / BN);
        sgemm_tn<<<grid, 256>>>(query, Wq, bq, nullptr, (float*)pQ,
                                Mq, Dm, Dm, scale);
    }
    // 2) K projection: g_K = source @ Wk^T + bk
    {
        dim3 grid((total + BM - 1) / BM, Dm / BN);
        sgemm_tn<<<grid, 256>>>(source, Wk, bk, nullptr, (float*)pK,
                                total, Dm, Dm, 1.0f);
        // 3) V projection
        sgemm_tn<<<grid, 256>>>(source, Wv, bv, nullptr, (float*)pV,
                                total, Dm, Dm, 1.0f);
    }
    // 4) attention partials (split over keys; ragged handled on-device)
    {
        int nsplit = (total + SPLIT_LEN - 1) / SPLIT_LEN;
        if (nsplit < 1) nsplit = 1;
        if (nsplit > MAX_SPLITS) nsplit = MAX_SPLITS;
        dim3 grid(nsplit, Hh, Bn);
        attn_partial<<<grid, 128>>>(offs, Bn, NQn);
    }
    // 5) combine partials
    {
        int tot = Bn * Hh * NQn;
        attn_combine<<<(tot + 127) / 128, 128>>>(offs, Bn, NQn);
    }
    // 6) output projection + bias + residual: out = g_ctx @ Wo^T + bo + query
    {
        dim3 grid((Mq + BM - 1) / BM, Dm / BN);
        sgemm_tn<<<grid, 256>>>((const float*)pC, Wo, bo, query, out,
                                Mq, Dm, Dm, 1.0f);
    }
}

// round 6
// speedup vs baseline: 2.1999x; 2.1999x over previous
#include <cuda_runtime.h>
#include <cuda_bf16.h>
#include <math.h>
#include <cstdint>

// ---------------- problem constants ----------------
#define Dm 256
#define Hh 8
#define HD 32
#define NQMAX 128
#define MAXB 16
#define MAX_TOTAL 65536
#define SPLIT_LEN 512
#define MAX_SPLITS 128

// ---------------- device scratch ----------------
__device__ float g_K[MAX_TOTAL * Dm];
__device__ float g_V[MAX_TOTAL * Dm];
__device__ float g_Q[MAXB * NQMAX * Dm];
__device__ float g_ctx[MAXB * NQMAX * Dm];
__device__ float g_ctx_part[(size_t)MAXB * Hh * MAX_SPLITS * NQMAX * HD];
__device__ float g_m_part[(size_t)MAXB * Hh * MAX_SPLITS * NQMAX];
__device__ float g_l_part[(size_t)MAXB * Hh * MAX_SPLITS * NQMAX];

// ================= helpers =================
__device__ __forceinline__ uint32_t smem_to_u32(const void* p) {
    uint32_t a;
    asm("{ .reg .u64 t; cvta.to.shared.u64 t, %1; cvt.u32.u64 %0, t; }" : "=r"(a) : "l"(p));
    return a;
}
#define SMEM_SWZ(off) ((off) ^ (((off) >> 3) & 0x70))

__device__ __forceinline__ uint32_t pack_bf16x2(float a, float b) {
    uint32_t r;
    asm("cvt.rn.bf16x2.f32 %0, %1, %2;" : "=r"(r) : "f"(b), "f"(a));
    return r;
}

// ldmatrix x4 (row-major 8x8 b16 tiles)
#define LDSM_X4(r, addr) \
    asm volatile("ldmatrix.sync.aligned.m8n8.x4.shared.b16 {%0,%1,%2,%3}, [%4];" \
        : "=r"((r)[0]), "=r"((r)[1]), "=r"((r)[2]), "=r"((r)[3]) : "r"(addr))

// HMMA bf16: D(16x8) += A(16x16,row) * B(16x8,col)
#define MMA_BF16(d, a, b0, b1) \
    asm volatile("mma.sync.aligned.m16n8k16.row.col.f32.bf16.bf16.f32 " \
        "{%0,%1,%2,%3}, {%4,%5,%6,%7}, {%8,%9}, {%0,%1,%2,%3};" \
        : "+f"((d)[0]), "+f"((d)[1]), "+f"((d)[2]), "+f"((d)[3]) \
        : "r"((a)[0]), "r"((a)[1]), "r"((a)[2]), "r"((a)[3]), "r"(b0), "r"(b1))

// packed f32x2 helpers
typedef unsigned long long u64t;
#define FMA2(d, a, b, c) asm("fma.rn.f32x2 %0, %1, %2, %3;" : "=l"(d) : "l"(a), "l"(b), "l"(c))
#define MUL2(d, a, b)    asm("mul.rn.f32x2 %0, %1, %2;"     : "=l"(d) : "l"(a), "l"(b))
__device__ __forceinline__ u64t pack2(float x, float y) {
    u64t v; asm("mov.b64 %0, {%1,%2};" : "=l"(v) : "f"(x), "f"(y)); return v;
}
__device__ __forceinline__ float2 unpack2(u64t v) {
    float2 f; asm("mov.b64 {%0,%1}, %2;" : "=f"(f.x), "=f"(f.y) : "l"(v)); return f;
}

// ================= bf16 HMMA K/V projection ==================
// CTA: 128 M-rows x 128 N-cols, computes BOTH outK and outV tiles.
// smem: A[4 kb][128][128B] + Wk[4][128][128B] + Wv[4][128][128B] = 192KB
#define KVSM_A  0
#define KVSM_BK (4 * 128 * 128)
#define KVSM_BV (2 * 4 * 128 * 128)
#define KVSM_TOTAL (3 * 4 * 128 * 128)

__global__ void __launch_bounds__(256, 1)
kv_proj_mma(const float* __restrict__ A,
            const float* __restrict__ Wk, const float* __restrict__ bkp,
            const float* __restrict__ Wv, const float* __restrict__ bvp,
            float* __restrict__ outK, float* __restrict__ outV, int M)
{
    extern __shared__ char smem[];
    const int tid = threadIdx.x;
    const int m0 = blockIdx.x * 128;
    const int n0 = blockIdx.y * 128;

    // ---- stage A tile (128 x 256 fp32 -> bf16, SW128, 4 k-blocks) ----
#pragma unroll 4
    for (int i = 0; i < 32; i++) {
        int idx = tid + 256 * i;
        int row = idx >> 6;
        int c4  = (idx & 63) * 4;
        int gm  = m0 + row;
        float4 v = (gm < M) ? *(const float4*)(A + (size_t)gm * 256 + c4)
                            : make_float4(0.f, 0.f, 0.f, 0.f);
        int kb = c4 >> 6, kin = c4 & 63;
        uint32_t off = (uint32_t)(row * 128 + kin * 2);
        *(uint2*)(smem + KVSM_A + kb * 16384 + SMEM_SWZ(off)) =
            make_uint2(pack_bf16x2(v.x, v.y), pack_bf16x2(v.z, v.w));
    }
    // ---- stage Wk / Wv tiles (128 n-rows x 256 k each) ----
#pragma unroll 4
    for (int i = 0; i < 32; i++) {
        int idx = tid + 256 * i;
        int row = idx >> 6;
        int c4  = (idx & 63) * 4;
        int kb = c4 >> 6, kin = c4 & 63;
        uint32_t swz = SMEM_SWZ((uint32_t)(row * 128 + kin * 2));
        float4 vk = *(const float4*)(Wk + (size_t)(n0 + row) * 256 + c4);
        float4 vv = *(const float4*)(Wv + (size_t)(n0 + row) * 256 + c4);
        *(uint2*)(smem + KVSM_BK + kb * 16384 + swz) =
            make_uint2(pack_bf16x2(vk.x, vk.y), pack_bf16x2(vk.z, vk.w));
        *(uint2*)(smem + KVSM_BV + kb * 16384 + swz) =
            make_uint2(pack_bf16x2(vv.x, vv.y), pack_bf16x2(vv.z, vv.w));
    }
    __syncthreads();

    // ---- mma phase: 8 warps, warp tile 32m x 64n, both matrices ----
    const int lane = tid & 31;
    const int wid  = tid >> 5;
    const int wm = (wid & 3) * 32;
    const int wn = (wid >> 2) * 64;
    const uint32_t sbase = smem_to_u32(smem);

    float accK[2][8][4], accV[2][8][4];
#pragma unroll
    for (int f = 0; f < 2; f++)
#pragma unroll
        for (int g = 0; g < 8; g++)
#pragma unroll
            for (int c = 0; c < 4; c++) { accK[f][g][c] = 0.f; accV[f][g][c] = 0.f; }

    const int a_row    = wm + (lane & 15);
    const int a_kchunk = (lane >> 4) * 8;               // elems
    const int b_row    = wn + ((lane >> 4) & 1) * 8 + (lane & 7);
    const int b_kchunk = ((lane >> 3) & 1) * 8;         // elems

#pragma unroll
    for (int kb = 0; kb < 4; kb++) {
        const uint32_t aBase = sbase + KVSM_A  + kb * 16384;
        const uint32_t kBase = sbase + KVSM_BK + kb * 16384;
        const uint32_t vBase = sbase + KVSM_BV + kb * 16384;
#pragma unroll
        for (int ks = 0; ks < 4; ks++) {
            const int kk = ks * 16;
            uint32_t a0r[4], a1r[4];
            {
                uint32_t off0 = (uint32_t)( a_row       * 128 + (kk + a_kchunk) * 2);
                uint32_t off1 = (uint32_t)((a_row + 16) * 128 + (kk + a_kchunk) * 2);
                LDSM_X4(a0r, aBase + SMEM_SWZ(off0));
                LDSM_X4(a1r, aBase + SMEM_SWZ(off1));
            }
            uint32_t bkf[4][4], bvf[4][4];
#pragma unroll
            for (int p = 0; p < 4; p++) {
                uint32_t off = (uint32_t)((b_row + p * 16) * 128 + (kk + b_kchunk) * 2);
                uint32_t swz = SMEM_SWZ(off);
                LDSM_X4(bkf[p], kBase + swz);
                LDSM_X4(bvf[p], vBase + swz);
            }
#pragma unroll
            for (int p = 0; p < 4; p++) {
                MMA_BF16(accK[0][2 * p],     a0r, bkf[p][0], bkf[p][1]);
                MMA_BF16(accK[0][2 * p + 1], a0r, bkf[p][2], bkf[p][3]);
                MMA_BF16(accK[1][2 * p],     a1r, bkf[p][0], bkf[p][1]);
                MMA_BF16(accK[1][2 * p + 1], a1r, bkf[p][2], bkf[p][3]);
                MMA_BF16(accV[0][2 * p],     a0r, bvf[p][0], bvf[p][1]);
                MMA_BF16(accV[0][2 * p + 1], a0r, bvf[p][2], bvf[p][3]);
                MMA_BF16(accV[1][2 * p],     a1r, bvf[p][0], bvf[p][1]);
                MMA_BF16(accV[1][2 * p + 1], a1r, bvf[p][2], bvf[p][3]);
            }
        }
    }

    // ---- epilogue: bias + store fp32 ----
#pragma unroll
    for (int f = 0; f < 2; f++) {
        const int mA = m0 + wm + f * 16 + (lane >> 2);
        const int mB = mA + 8;
#pragma unroll
        for (int g = 0; g < 8; g++) {
            const int n = n0 + wn + g * 8 + (lane & 3) * 2;
            const float bk0 = bkp[n], bk1 = bkp[n + 1];
            const float bv0 = bvp[n], bv1 = bvp[n + 1];
            if (mA < M) {
                *(float2*)(outK + (size_t)mA * 256 + n) =
                    make_float2(accK[f][g][0] + bk0, accK[f][g][1] + bk1);
                *(float2*)(outV + (size_t)mA * 256 + n) =
                    make_float2(accV[f][g][0] + bv0, accV[f][g][1] + bv1);
            }
            if (mB < M) {
                *(float2*)(outK + (size_t)mB * 256 + n) =
                    make_float2(accK[f][g][2] + bk0, accK[f][g][3] + bk1);
                *(float2*)(outV + (size_t)mB * 256 + n) =
                    make_float2(accV[f][g][2] + bv0, accV[f][g][3] + bv1);
            }
        }
    }
}

// ================= fp32 SGEMM (small mats: Q-proj, out-proj) =================
#define BM 128
#define BN 64
#define BK 32
__global__ __launch_bounds__(256)
void sgemm_tn(const float* __restrict__ A, const float* __restrict__ W,
              const float* __restrict__ bias, const float* __restrict__ resid,
              float* __restrict__ out, int M, int N, int K, float alpha)
{
    __shared__ float As[BK][BM + 4];
    __shared__ float Ws[BK][BN + 4];
    const int t = threadIdx.x, tx = t & 15, ty = t >> 4;
    const int m0 = blockIdx.x * BM, n0 = blockIdx.y * BN;
    float acc[8][4];
#pragma unroll
    for (int i = 0; i < 8; i++)
#pragma unroll
        for (int j = 0; j < 4; j++) acc[i][j] = 0.f;
    const int ar = t >> 3, ac = (t & 7) * 4;
    for (int k0 = 0; k0 < K; k0 += BK) {
#pragma unroll
        for (int i = 0; i < 4; i++) {
            int row = ar + 32 * i, gm = m0 + row;
            float4 v = make_float4(0.f, 0.f, 0.f, 0.f);
            if (gm < M) v = *(const float4*)(A + (size_t)gm * K + k0 + ac);
            As[ac + 0][row] = v.x; As[ac + 1][row] = v.y;
            As[ac + 2][row] = v.z; As[ac + 3][row] = v.w;
        }
#pragma unroll
        for (int i = 0; i < 2; i++) {
            int n = ar + 32 * i;
            float4 v = *(const float4*)(W + (size_t)(n0 + n) * K + k0 + ac);
            Ws[ac + 0][n] = v.x; Ws[ac + 1][n] = v.y;
            Ws[ac + 2][n] = v.z; Ws[ac + 3][n] = v.w;
        }
        __syncthreads();
#pragma unroll
        for (int kk = 0; kk < BK; kk++) {
            float a[8], w[4];
#pragma unroll
            for (int i = 0; i < 8; i++) a[i] = As[kk][ty * 8 + i];
#pragma unroll
            for (int j = 0; j < 4; j++) w[j] = Ws[kk][tx * 4 + j];
#pragma unroll
            for (int i = 0; i < 8; i++)
#pragma unroll
                for (int j = 0; j < 4; j++) acc[i][j] = fmaf(a[i], w[j], acc[i][j]);
        }
        __syncthreads();
    }
#pragma unroll
    for (int i = 0; i < 8; i++) {
        int gm = m0 + ty * 8 + i;
        if (gm >= M) continue;
#pragma unroll
        for (int j = 0; j < 4; j++) {
            int gn = n0 + tx * 4 + j;
            float v = acc[i][j];
            if (bias) v += bias[gn];
            v *= alpha;
            if (resid) v += resid[(size_t)gm * N + gn];
            out[(size_t)gm * N + gn] = v;
        }
    }
}

// ================= split-K flash attention partials (f32x2) =================
#define TK 64
__global__ __launch_bounds__(128)
void attn_partial(const int* __restrict__ offs, int Bn, int NQn)
{
    const int s = blockIdx.x, h = blockIdx.y, b = blockIdx.z;
    const int tid = threadIdx.x;
    const int beg = offs[b];
    const int len = offs[b + 1] - beg;
    const int k0  = s * SPLIT_LEN;
    if (k0 >= len) return;
    const int kend = min(k0 + SPLIT_LEN, len);

    __shared__ float Ks[TK][HD];
    __shared__ float Vs[TK][HD];

    u64t q2[16];
    if (tid < NQn) {
        const float* qp = g_Q + ((size_t)(b * NQn + tid)) * Dm + h * HD;
#pragma unroll
        for (int d = 0; d < 16; d++) q2[d] = *(const u64t*)(qp + 2 * d);
    } else {
#pragma unroll
        for (int d = 0; d < 16; d++) q2[d] = 0ull;
    }
    u64t acc2[16];
#pragma unroll
    for (int d = 0; d < 16; d++) acc2[d] = 0ull;
    float m = -1e30f, l = 0.f;

    for (int kt = k0; kt < kend; kt += TK) {
        const int nk = min(TK, kend - kt);
#pragma unroll
        for (int i = 0; i < 4; i++) {
            int idx = tid + 128 * i;
            int row = idx >> 3;
            int c4  = (idx & 7) * 4;
            if (row < nk) {
                size_t gb = ((size_t)(beg + kt + row)) * Dm + h * HD + c4;
                *(float4*)&Ks[row][c4] = *(const float4*)(g_K + gb);
                *(float4*)&Vs[row][c4] = *(const float4*)(g_V + gb);
            } else {
                *(float4*)&Ks[row][c4] = make_float4(0.f, 0.f, 0.f, 0.f);
                *(float4*)&Vs[row][c4] = make_float4(0.f, 0.f, 0.f, 0.f);
            }
        }
        __syncthreads();

        if (tid < NQn) {
            for (int i0 = 0; i0 < nk; i0 += 8) {
                u64t s2[8];
#pragma unroll
                for (int jj = 0; jj < 8; jj++) s2[jj] = 0ull;
#pragma unroll
                for (int d4 = 0; d4 < 8; d4++) {
#pragma unroll
                    for (int jj = 0; jj < 8; jj++) {
                        ulonglong2 kk = *(const ulonglong2*)&Ks[i0 + jj][d4 * 4];
                        FMA2(s2[jj], q2[2 * d4 + 0], kk.x, s2[jj]);
                        FMA2(s2[jj], q2[2 * d4 + 1], kk.y, s2[jj]);
                    }
                }
                float sc[8];
#pragma unroll
                for (int jj = 0; jj < 8; jj++) {
                    float2 f = unpack2(s2[jj]);
                    sc[jj] = (i0 + jj < nk) ? (f.x + f.y) : -3e30f;
                }
                float mx = sc[0];
#pragma unroll
                for (int jj = 1; jj < 8; jj++) mx = fmaxf(mx, sc[jj]);
                if (mx > m) {
                    float corr = __expf(m - mx);
                    m = mx;
                    l *= corr;
                    u64t c2 = pack2(corr, corr);
#pragma unroll
                    for (int d = 0; d < 16; d++) MUL2(acc2[d], acc2[d], c2);
                }
                u64t p2[8];
                float psum = 0.f;
#pragma unroll
                for (int jj = 0; jj < 8; jj++) {
                    float p = __expf(sc[jj] - m);
                    psum += p;
                    p2[jj] = pack2(p, p);
                }
                l += psum;
#pragma unroll
                for (int d4 = 0; d4 < 8; d4++) {
#pragma unroll
                    for (int jj = 0; jj < 8; jj++) {
                        ulonglong2 vv = *(const ulonglong2*)&Vs[i0 + jj][d4 * 4];
                        FMA2(acc2[2 * d4 + 0], p2[jj], vv.x, acc2[2 * d4 + 0]);
                        FMA2(acc2[2 * d4 + 1], p2[jj], vv.y, acc2[2 * d4 + 1]);
                    }
                }
            }
        }
        __syncthreads();
    }

    if (tid < NQn) {
        size_t pbase = ((size_t)(b * Hh + h) * MAX_SPLITS + s);
        g_m_part[pbase * NQMAX + tid] = m;
        g_l_part[pbase * NQMAX + tid] = l;
        u64t* cp = (u64t*)(g_ctx_part + (pbase * NQMAX + tid) * HD);
#pragma unroll
        for (int d = 0; d < 16; d++) cp[d] = acc2[d];
    }
}

// ================= combine split partials =================
__global__ __launch_bounds__(128)
void attn_combine(const int* __restrict__ offs, int Bn, int NQn)
{
    int idx = blockIdx.x * blockDim.x + threadIdx.x;
    int tot = Bn * Hh * NQn;
    if (idx >= tot) return;
    int q  = idx % NQn;
    int bh = idx / NQn;
    int b  = bh / Hh;

    int len = offs[b + 1] - offs[b];
    float ctx[HD];
#pragma unroll
    for (int j = 0; j < HD; j++) ctx[j] = 0.f;

    if (len > 0) {
        size_t base = (size_t)bh * MAX_SPLITS;
        float M = -1e30f;
        for (int s = 0; s < MAX_SPLITS && s * SPLIT_LEN < len; s++)
            M = fmaxf(M, g_m_part[(base + s) * NQMAX + q]);
        float L = 0.f;
        for (int s = 0; s < MAX_SPLITS && s * SPLIT_LEN < len; s++) {
            float w = __expf(g_m_part[(base + s) * NQMAX + q] - M);
            L += w * g_l_part[(base + s) * NQMAX + q];
            const float* cp = g_ctx_part + ((base + s) * NQMAX + q) * HD;
#pragma unroll
            for (int j = 0; j < HD; j++) ctx[j] = fmaf(w, cp[j], ctx[j]);
        }
        float inv = 1.f / L;
#pragma unroll
        for (int j = 0; j < HD; j++) ctx[j] *= inv;
    }
    int h = bh % Hh;
    float* op = g_ctx + ((size_t)b * NQn + q) * Dm + h * HD;
#pragma unroll
    for (int j = 0; j < HD; j++) op[j] = ctx[j];
}

// ================= launch =================
extern "C" void kernel_launch(void* const* d_in, const int* in_sizes, int n_in,
                              void* d_out, int out_size)
{
    const float* source = (const float*)d_in[0];
    const float* query  = (const float*)d_in[1];
    const int*   offs   = (const int*)  d_in[2];
    const float* Wq = (const float*)d_in[3];  const float* bq = (const float*)d_in[4];
    const float* Wk = (const float*)d_in[5];  const float* bk = (const float*)d_in[6];
    const float* Wv = (const float*)d_in[7];  const float* bv = (const float*)d_in[8];
    const float* Wo = (const float*)d_in[9];  const float* bo = (const float*)d_in[10];
    float* out = (float*)d_out;

    const int total = in_sizes[0] / Dm;
    const int Bn    = in_sizes[2] - 1;
    const int NQn   = in_sizes[1] / (Bn * Dm);
    const int Mq    = Bn * NQn;
    const float scale = rsqrtf((float)HD);

    void *pK, *pV, *pQ, *pC;
    cudaGetSymbolAddress(&pK, g_K);
    cudaGetSymbolAddress(&pV, g_V);
    cudaGetSymbolAddress(&pQ, g_Q);
    cudaGetSymbolAddress(&pC, g_ctx);

    cudaFuncSetAttribute(kv_proj_mma, cudaFuncAttributeMaxDynamicSharedMemorySize,
                         KVSM_TOTAL);

    // 1) Q projection (scale folded in)
    {
        dim3 grid((Mq + BM - 1) / BM, Dm / BN);
        sgemm_tn<<<grid, 256>>>(query, Wq, bq, nullptr, (float*)pQ, Mq, Dm, Dm, scale);
    }
    // 2+3) K & V projections via bf16 HMMA (both in one kernel)
    {
        dim3 grid((total + 127) / 128, 2);
        kv_proj_mma<<<grid, 256, KVSM_TOTAL>>>(source, Wk, bk, Wv, bv,
                                               (float*)pK, (float*)pV, total);
    }
    // 4) attention partials
    {
        int nsplit = (total + SPLIT_LEN - 1) / SPLIT_LEN;
        if (nsplit < 1) nsplit = 1;
        if (nsplit > MAX_SPLITS) nsplit = MAX_SPLITS;
        dim3 grid(nsplit, Hh, Bn);
        attn_partial<<<grid, 128>>>(offs, Bn, NQn);
    }
    // 5) combine
    {
        int tot = Bn * Hh * NQn;
        attn_combine<<<(tot + 127) / 128, 128>>>(offs, Bn, NQn);
    }
    // 6) output projection + bias + residual
    {
        dim3 grid((Mq + BM - 1) / BM, Dm / BN);
        sgemm_tn<<<grid, 256>>>((const float*)pC, Wo, bo, query, out, Mq, Dm, Dm, 1.0f);
    }
}

// round 7
// speedup vs baseline: 4.4291x; 2.0133x over previous
#include <cuda_runtime.h>
#include <cuda_bf16.h>
#include <math.h>
#include <cstdint>

// ---------------- problem constants ----------------
#define Dm 256
#define Hh 8
#define HD 32
#define NQMAX 128
#define MAXB 16
#define MAX_TOTAL 65536
#define SPLIT_LEN 512
#define MAX_SPLITS 128

// ---------------- device scratch ----------------
__device__ float g_K[MAX_TOTAL * Dm];
__device__ float g_V[MAX_TOTAL * Dm];
__device__ float g_Q[MAXB * NQMAX * Dm];
__device__ float g_ctx[MAXB * NQMAX * Dm];
__device__ float g_ctx_part[(size_t)MAXB * Hh * MAX_SPLITS * NQMAX * HD];
__device__ float g_m_part[(size_t)MAXB * Hh * MAX_SPLITS * NQMAX];
__device__ float g_l_part[(size_t)MAXB * Hh * MAX_SPLITS * NQMAX];

// ================= helpers =================
__device__ __forceinline__ uint32_t smem_to_u32(const void* p) {
    uint32_t a;
    asm("{ .reg .u64 t; cvta.to.shared.u64 t, %1; cvt.u32.u64 %0, t; }" : "=r"(a) : "l"(p));
    return a;
}
#define SMEM_SWZ(off) ((off) ^ (((off) >> 3) & 0x70))

__device__ __forceinline__ uint32_t pack_bf16x2(float a, float b) {
    uint32_t r;
    asm("cvt.rn.bf16x2.f32 %0, %1, %2;" : "=r"(r) : "f"(b), "f"(a));
    return r;
}

// ldmatrix x4 (row-major 8x8 b16 tiles)
#define LDSM_X4(r, addr) \
    asm volatile("ldmatrix.sync.aligned.m8n8.x4.shared.b16 {%0,%1,%2,%3}, [%4];" \
        : "=r"((r)[0]), "=r"((r)[1]), "=r"((r)[2]), "=r"((r)[3]) : "r"(addr))
#define LDSM_X4_T(r, addr) \
    asm volatile("ldmatrix.sync.aligned.m8n8.x4.trans.shared.b16 {%0,%1,%2,%3}, [%4];" \
        : "=r"((r)[0]), "=r"((r)[1]), "=r"((r)[2]), "=r"((r)[3]) : "r"(addr))

// HMMA bf16: D(16x8) += A(16x16,row) * B(16x8,col)
#define MMA_BF16(d, a, b0, b1) \
    asm volatile("mma.sync.aligned.m16n8k16.row.col.f32.bf16.bf16.f32 " \
        "{%0,%1,%2,%3}, {%4,%5,%6,%7}, {%8,%9}, {%0,%1,%2,%3};" \
        : "+f"((d)[0]), "+f"((d)[1]), "+f"((d)[2]), "+f"((d)[3]) \
        : "r"((a)[0]), "r"((a)[1]), "r"((a)[2]), "r"((a)[3]), "r"(b0), "r"(b1))

// ================= bf16 HMMA K/V projection (unchanged from R6) ==========
#define KVSM_A  0
#define KVSM_BK (4 * 128 * 128)
#define KVSM_BV (2 * 4 * 128 * 128)
#define KVSM_TOTAL (3 * 4 * 128 * 128)

__global__ void __launch_bounds__(256, 1)
kv_proj_mma(const float* __restrict__ A,
            const float* __restrict__ Wk, const float* __restrict__ bkp,
            const float* __restrict__ Wv, const float* __restrict__ bvp,
            float* __restrict__ outK, float* __restrict__ outV, int M)
{
    extern __shared__ char smem[];
    const int tid = threadIdx.x;
    const int m0 = blockIdx.x * 128;
    const int n0 = blockIdx.y * 128;

#pragma unroll 4
    for (int i = 0; i < 32; i++) {
        int idx = tid + 256 * i;
        int row = idx >> 6;
        int c4  = (idx & 63) * 4;
        int gm  = m0 + row;
        float4 v = (gm < M) ? *(const float4*)(A + (size_t)gm * 256 + c4)
                            : make_float4(0.f, 0.f, 0.f, 0.f);
        int kb = c4 >> 6, kin = c4 & 63;
        uint32_t off = (uint32_t)(row * 128 + kin * 2);
        *(uint2*)(smem + KVSM_A + kb * 16384 + SMEM_SWZ(off)) =
            make_uint2(pack_bf16x2(v.x, v.y), pack_bf16x2(v.z, v.w));
    }
#pragma unroll 4
    for (int i = 0; i < 32; i++) {
        int idx = tid + 256 * i;
        int row = idx >> 6;
        int c4  = (idx & 63) * 4;
        int kb = c4 >> 6, kin = c4 & 63;
        uint32_t swz = SMEM_SWZ((uint32_t)(row * 128 + kin * 2));
        float4 vk = *(const float4*)(Wk + (size_t)(n0 + row) * 256 + c4);
        float4 vv = *(const float4*)(Wv + (size_t)(n0 + row) * 256 + c4);
        *(uint2*)(smem + KVSM_BK + kb * 16384 + swz) =
            make_uint2(pack_bf16x2(vk.x, vk.y), pack_bf16x2(vk.z, vk.w));
        *(uint2*)(smem + KVSM_BV + kb * 16384 + swz) =
            make_uint2(pack_bf16x2(vv.x, vv.y), pack_bf16x2(vv.z, vv.w));
    }
    __syncthreads();

    const int lane = tid & 31;
    const int wid  = tid >> 5;
    const int wm = (wid & 3) * 32;
    const int wn = (wid >> 2) * 64;
    const uint32_t sbase = smem_to_u32(smem);

    float accK[2][8][4], accV[2][8][4];
#pragma unroll
    for (int f = 0; f < 2; f++)
#pragma unroll
        for (int g = 0; g < 8; g++)
#pragma unroll
            for (int c = 0; c < 4; c++) { accK[f][g][c] = 0.f; accV[f][g][c] = 0.f; }

    const int a_row    = wm + (lane & 15);
    const int a_kchunk = (lane >> 4) * 8;
    const int b_row    = wn + ((lane >> 4) & 1) * 8 + (lane & 7);
    const int b_kchunk = ((lane >> 3) & 1) * 8;

#pragma unroll
    for (int kb = 0; kb < 4; kb++) {
        const uint32_t aBase = sbase + KVSM_A  + kb * 16384;
        const uint32_t kBase = sbase + KVSM_BK + kb * 16384;
        const uint32_t vBase = sbase + KVSM_BV + kb * 16384;
#pragma unroll
        for (int ks = 0; ks < 4; ks++) {
            const int kk = ks * 16;
            uint32_t a0r[4], a1r[4];
            {
                uint32_t off0 = (uint32_t)( a_row       * 128 + (kk + a_kchunk) * 2);
                uint32_t off1 = (uint32_t)((a_row + 16) * 128 + (kk + a_kchunk) * 2);
                LDSM_X4(a0r, aBase + SMEM_SWZ(off0));
                LDSM_X4(a1r, aBase + SMEM_SWZ(off1));
            }
            uint32_t bkf[4][4], bvf[4][4];
#pragma unroll
            for (int p = 0; p < 4; p++) {
                uint32_t off = (uint32_t)((b_row + p * 16) * 128 + (kk + b_kchunk) * 2);
                uint32_t swz = SMEM_SWZ(off);
                LDSM_X4(bkf[p], kBase + swz);
                LDSM_X4(bvf[p], vBase + swz);
            }
#pragma unroll
            for (int p = 0; p < 4; p++) {
                MMA_BF16(accK[0][2 * p],     a0r, bkf[p][0], bkf[p][1]);
                MMA_BF16(accK[0][2 * p + 1], a0r, bkf[p][2], bkf[p][3]);
                MMA_BF16(accK[1][2 * p],     a1r, bkf[p][0], bkf[p][1]);
                MMA_BF16(accK[1][2 * p + 1], a1r, bkf[p][2], bkf[p][3]);
                MMA_BF16(accV[0][2 * p],     a0r, bvf[p][0], bvf[p][1]);
                MMA_BF16(accV[0][2 * p + 1], a0r, bvf[p][2], bvf[p][3]);
                MMA_BF16(accV[1][2 * p],     a1r, bvf[p][0], bvf[p][1]);
                MMA_BF16(accV[1][2 * p + 1], a1r, bvf[p][2], bvf[p][3]);
            }
        }
    }

#pragma unroll
    for (int f = 0; f < 2; f++) {
        const int mA = m0 + wm + f * 16 + (lane >> 2);
        const int mB = mA + 8;
#pragma unroll
        for (int g = 0; g < 8; g++) {
            const int n = n0 + wn + g * 8 + (lane & 3) * 2;
            const float bk0 = bkp[n], bk1 = bkp[n + 1];
            const float bv0 = bvp[n], bv1 = bvp[n + 1];
            if (mA < M) {
                *(float2*)(outK + (size_t)mA * 256 + n) =
                    make_float2(accK[f][g][0] + bk0, accK[f][g][1] + bk1);
                *(float2*)(outV + (size_t)mA * 256 + n) =
                    make_float2(accV[f][g][0] + bv0, accV[f][g][1] + bv1);
            }
            if (mB < M) {
                *(float2*)(outK + (size_t)mB * 256 + n) =
                    make_float2(accK[f][g][2] + bk0, accK[f][g][3] + bk1);
                *(float2*)(outV + (size_t)mB * 256 + n) =
                    make_float2(accV[f][g][2] + bv0, accV[f][g][3] + bv1);
            }
        }
    }
}

// ================= fp32 SGEMM (small mats: Q-proj, out-proj) =================
#define BM 128
#define BN 64
#define BK 32
__global__ __launch_bounds__(256)
void sgemm_tn(const float* __restrict__ A, const float* __restrict__ W,
              const float* __restrict__ bias, const float* __restrict__ resid,
              float* __restrict__ out, int M, int N, int K, float alpha)
{
    __shared__ float As[BK][BM + 4];
    __shared__ float Ws[BK][BN + 4];
    const int t = threadIdx.x, tx = t & 15, ty = t >> 4;
    const int m0 = blockIdx.x * BM, n0 = blockIdx.y * BN;
    float acc[8][4];
#pragma unroll
    for (int i = 0; i < 8; i++)
#pragma unroll
        for (int j = 0; j < 4; j++) acc[i][j] = 0.f;
    const int ar = t >> 3, ac = (t & 7) * 4;
    for (int k0 = 0; k0 < K; k0 += BK) {
#pragma unroll
        for (int i = 0; i < 4; i++) {
            int row = ar + 32 * i, gm = m0 + row;
            float4 v = make_float4(0.f, 0.f, 0.f, 0.f);
            if (gm < M) v = *(const float4*)(A + (size_t)gm * K + k0 + ac);
            As[ac + 0][row] = v.x; As[ac + 1][row] = v.y;
            As[ac + 2][row] = v.z; As[ac + 3][row] = v.w;
        }
#pragma unroll
        for (int i = 0; i < 2; i++) {
            int n = ar + 32 * i;
            float4 v = *(const float4*)(W + (size_t)(n0 + n) * K + k0 + ac);
            Ws[ac + 0][n] = v.x; Ws[ac + 1][n] = v.y;
            Ws[ac + 2][n] = v.z; Ws[ac + 3][n] = v.w;
        }
        __syncthreads();
#pragma unroll
        for (int kk = 0; kk < BK; kk++) {
            float a[8], w[4];
#pragma unroll
            for (int i = 0; i < 8; i++) a[i] = As[kk][ty * 8 + i];
#pragma unroll
            for (int j = 0; j < 4; j++) w[j] = Ws[kk][tx * 4 + j];
#pragma unroll
            for (int i = 0; i < 8; i++)
#pragma unroll
                for (int j = 0; j < 4; j++) acc[i][j] = fmaf(a[i], w[j], acc[i][j]);
        }
        __syncthreads();
    }
#pragma unroll
    for (int i = 0; i < 8; i++) {
        int gm = m0 + ty * 8 + i;
        if (gm >= M) continue;
#pragma unroll
        for (int j = 0; j < 4; j++) {
            int gn = n0 + tx * 4 + j;
            float v = acc[i][j];
            if (bias) v += bias[gn];
            v *= alpha;
            if (resid) v += resid[(size_t)gm * N + gn];
            out[(size_t)gm * N + gn] = v;
        }
    }
}

// ================= HMMA flash-attention partials ==========================
// CTA = (split, head, batch). 4 warps x 32 query rows = 128-query tile.
// 64-key chunks: S = Q@K^T (HMMA), online softmax, ctx += P@V (HMMA).
#define TK 64
#define KROWB 80   /* smem row stride bytes (40 bf16): conflict-free ldmatrix */

__global__ void __launch_bounds__(128, 2)
attn_partial(const int* __restrict__ offs, int Bn, int NQn)
{
    const int s = blockIdx.x, h = blockIdx.y, b = blockIdx.z;
    const int tid = threadIdx.x;
    const int lane = tid & 31, wid = tid >> 5;
    const int beg = offs[b];
    const int len = offs[b + 1] - beg;
    const int k0  = s * SPLIT_LEN;
    if (k0 >= len) return;
    const int kend = min(k0 + SPLIT_LEN, len);

    __shared__ __align__(16) char sKm[TK * KROWB];
    __shared__ __align__(16) char sVm[TK * KROWB];
    const uint32_t sK = smem_to_u32(sKm);
    const uint32_t sV = smem_to_u32(sVm);

    const int wm = wid * 32;          // warp's query-row base (0..96)

    // ---- Q fragments (A-frag m16k16), scale+bias already folded into g_Q ----
    uint32_t qa[2][2][4];
#pragma unroll
    for (int f = 0; f < 2; f++)
#pragma unroll
        for (int c = 0; c < 2; c++) {
            const int col = h * HD + c * 16 + 2 * (lane & 3);
#pragma unroll
            for (int e = 0; e < 4; e++) {
                int row = wm + 16 * f + (lane >> 2) + (e & 1) * 8;
                int cc  = col + (e >> 1) * 8;
                uint32_t v = 0;
                if (row < NQn) {
                    float2 qv = *(const float2*)(g_Q + ((size_t)(b * NQn + row)) * Dm + cc);
                    v = pack_bf16x2(qv.x, qv.y);
                }
                qa[f][c][e] = v;
            }
        }

    float o[2][4][4];
#pragma unroll
    for (int f = 0; f < 2; f++)
#pragma unroll
        for (int j = 0; j < 4; j++)
#pragma unroll
            for (int e = 0; e < 4; e++) o[f][j][e] = 0.f;
    float mrow[2][2], lrow[2][2];
#pragma unroll
    for (int f = 0; f < 2; f++) { mrow[f][0] = mrow[f][1] = -1e30f; lrow[f][0] = lrow[f][1] = 0.f; }

    const int grp = lane >> 3, lr = lane & 7;

    for (int kt = k0; kt < kend; kt += TK) {
        const int nv = min(TK, kend - kt);
        // ---- stage K/V chunk (fp32 -> bf16, 80B rows) ----
#pragma unroll
        for (int it = 0; it < 4; it++) {
            int idx = tid + 128 * it;       // 0..511
            int row = idx >> 3;
            int c4  = (idx & 7) * 4;
            uint2 kk = make_uint2(0u, 0u), vv = make_uint2(0u, 0u);
            if (row < nv) {
                size_t gb = (size_t)(beg + kt + row) * Dm + h * HD + c4;
                float4 kf = *(const float4*)(g_K + gb);
                float4 vf = *(const float4*)(g_V + gb);
                kk = make_uint2(pack_bf16x2(kf.x, kf.y), pack_bf16x2(kf.z, kf.w));
                vv = make_uint2(pack_bf16x2(vf.x, vf.y), pack_bf16x2(vf.z, vf.w));
            }
            *(uint2*)(sKm + row * KROWB + c4 * 2) = kk;
            *(uint2*)(sVm + row * KROWB + c4 * 2) = vv;
        }
        __syncthreads();

        // ---- S = Q @ K^T ----
        float sc[2][8][4];
#pragma unroll
        for (int f = 0; f < 2; f++)
#pragma unroll
            for (int nt = 0; nt < 8; nt++)
#pragma unroll
                for (int e = 0; e < 4; e++) sc[f][nt][e] = 0.f;

#pragma unroll
        for (int c = 0; c < 2; c++) {
#pragma unroll
            for (int p = 0; p < 4; p++) {
                // K b-frags: lanes0-7 keys p16+lr hd c16 | 8-15 same keys hd+8
                //            | 16-23 keys+8 hd | 24-31 keys+8 hd+8
                int krow = p * 16 + (grp >> 1) * 8 + lr;
                int hdo  = c * 16 + (grp & 1) * 8;
                uint32_t kb[4];
                LDSM_X4(kb, sK + krow * KROWB + hdo * 2);
#pragma unroll
                for (int f = 0; f < 2; f++) {
                    MMA_BF16(sc[f][2 * p],     qa[f][c], kb[0], kb[1]);
                    MMA_BF16(sc[f][2 * p + 1], qa[f][c], kb[2], kb[3]);
                }
            }
        }

        // ---- mask padded keys (only on ragged tail chunk) ----
        if (nv < TK) {
#pragma unroll
            for (int nt = 0; nt < 8; nt++) {
                int c0 = nt * 8 + 2 * (lane & 3);
#pragma unroll
                for (int f = 0; f < 2; f++) {
                    if (c0     >= nv) { sc[f][nt][0] = -3e30f; sc[f][nt][2] = -3e30f; }
                    if (c0 + 1 >= nv) { sc[f][nt][1] = -3e30f; sc[f][nt][3] = -3e30f; }
                }
            }
        }

        // ---- online softmax (per row: quad shfl reduce) ----
#pragma unroll
        for (int f = 0; f < 2; f++) {
#pragma unroll
            for (int half = 0; half < 2; half++) {
                float mx = -3e30f;
#pragma unroll
                for (int nt = 0; nt < 8; nt++)
                    mx = fmaxf(mx, fmaxf(sc[f][nt][2 * half], sc[f][nt][2 * half + 1]));
                mx = fmaxf(mx, __shfl_xor_sync(0xffffffffu, mx, 1));
                mx = fmaxf(mx, __shfl_xor_sync(0xffffffffu, mx, 2));
                float mnew = fmaxf(mrow[f][half], mx);
                float corr = __expf(mrow[f][half] - mnew);
                mrow[f][half] = mnew;
                lrow[f][half] *= corr;
#pragma unroll
                for (int j = 0; j < 4; j++) {
                    o[f][j][2 * half]     *= corr;
                    o[f][j][2 * half + 1] *= corr;
                }
                float rs = 0.f;
#pragma unroll
                for (int nt = 0; nt < 8; nt++) {
                    float p0 = __expf(sc[f][nt][2 * half]     - mnew);
                    float p1 = __expf(sc[f][nt][2 * half + 1] - mnew);
                    sc[f][nt][2 * half] = p0; sc[f][nt][2 * half + 1] = p1;
                    rs += p0 + p1;
                }
                rs += __shfl_xor_sync(0xffffffffu, rs, 1);
                rs += __shfl_xor_sync(0xffffffffu, rs, 2);
                lrow[f][half] += rs;
            }
        }

        // ---- P -> bf16 A-frags (C-frag pair == A-frag identity) ----
        uint32_t pa[2][4][4];
#pragma unroll
        for (int f = 0; f < 2; f++)
#pragma unroll
            for (int kc = 0; kc < 4; kc++) {
                pa[f][kc][0] = pack_bf16x2(sc[f][2 * kc][0],     sc[f][2 * kc][1]);
                pa[f][kc][1] = pack_bf16x2(sc[f][2 * kc][2],     sc[f][2 * kc][3]);
                pa[f][kc][2] = pack_bf16x2(sc[f][2 * kc + 1][0], sc[f][2 * kc + 1][1]);
                pa[f][kc][3] = pack_bf16x2(sc[f][2 * kc + 1][2], sc[f][2 * kc + 1][3]);
            }

        // ---- ctx += P @ V ----
#pragma unroll
        for (int kc = 0; kc < 4; kc++) {
#pragma unroll
            for (int vt = 0; vt < 2; vt++) {
                // V b-frags (trans): lanes0-7 keys kc16+lr hd vt16 | 8-15 keys+8 |
                //                    16-23 keys hd+8 | 24-31 keys+8 hd+8
                int krow = kc * 16 + (grp & 1) * 8 + lr;
                int hdo  = vt * 16 + (grp >> 1) * 8;
                uint32_t vb[4];
                LDSM_X4_T(vb, sV + krow * KROWB + hdo * 2);
#pragma unroll
                for (int f = 0; f < 2; f++) {
                    MMA_BF16(o[f][2 * vt],     pa[f][kc], vb[0], vb[1]);
                    MMA_BF16(o[f][2 * vt + 1], pa[f][kc], vb[2], vb[3]);
                }
            }
        }
        __syncthreads();
    }

    // ---- write partials ----
    const size_t pbase = ((size_t)(b * Hh + h) * MAX_SPLITS + s);
#pragma unroll
    for (int f = 0; f < 2; f++)
#pragma unroll
        for (int half = 0; half < 2; half++) {
            int row = wm + 16 * f + 8 * half + (lane >> 2);
            if (row < NQn) {
                if ((lane & 3) == 0) {
                    g_m_part[pbase * NQMAX + row] = mrow[f][half];
                    g_l_part[pbase * NQMAX + row] = lrow[f][half];
                }
#pragma unroll
                for (int j = 0; j < 4; j++) {
                    int d = j * 8 + 2 * (lane & 3);
                    *(float2*)(g_ctx_part + (pbase * NQMAX + row) * HD + d) =
                        make_float2(o[f][j][2 * half], o[f][j][2 * half + 1]);
                }
            }
        }
}

// ================= combine split partials (warp per (b,h,q)) ==============
__global__ __launch_bounds__(256)
void attn_combine(const int* __restrict__ offs, int Bn, int NQn)
{
    const int gwarp = (blockIdx.x * blockDim.x + threadIdx.x) >> 5;
    const int lane  = threadIdx.x & 31;
    const int tot = Bn * Hh * NQn;
    if (gwarp >= tot) return;
    const int q  = gwarp % NQn;
    const int bh = gwarp / NQn;
    const int b  = bh / Hh, h = bh % Hh;

    const int len = offs[b + 1] - offs[b];
    int ns = (len > 0) ? min((len + SPLIT_LEN - 1) / SPLIT_LEN, MAX_SPLITS) : 0;

    const size_t base = (size_t)bh * MAX_SPLITS;
    float M = -1e30f;
    for (int s2 = lane; s2 < ns; s2 += 32)
        M = fmaxf(M, g_m_part[(base + s2) * NQMAX + q]);
#pragma unroll
    for (int od = 16; od; od >>= 1) M = fmaxf(M, __shfl_xor_sync(0xffffffffu, M, od));

    float L = 0.f;
    for (int s2 = lane; s2 < ns; s2 += 32)
        L += __expf(g_m_part[(base + s2) * NQMAX + q] - M) * g_l_part[(base + s2) * NQMAX + q];
#pragma unroll
    for (int od = 16; od; od >>= 1) L += __shfl_xor_sync(0xffffffffu, L, od);

    float ctx = 0.f;                      // lane == hd index (HD == 32)
    for (int s2 = 0; s2 < ns; s2++) {
        float w = __expf(g_m_part[(base + s2) * NQMAX + q] - M);
        ctx += w * g_ctx_part[((base + s2) * NQMAX + q) * HD + lane];
    }
    float inv = (ns > 0 && L > 0.f) ? 1.f / L : 0.f;
    g_ctx[((size_t)b * NQn + q) * Dm + h * HD + lane] = ctx * inv;
}

// ================= launch =================
extern "C" void kernel_launch(void* const* d_in, const int* in_sizes, int n_in,
                              void* d_out, int out_size)
{
    const float* source = (const float*)d_in[0];
    const float* query  = (const float*)d_in[1];
    const int*   offs   = (const int*)  d_in[2];
    const float* Wq = (const float*)d_in[3];  const float* bq = (const float*)d_in[4];
    const float* Wk = (const float*)d_in[5];  const float* bk = (const float*)d_in[6];
    const float* Wv = (const float*)d_in[7];  const float* bv = (const float*)d_in[8];
    const float* Wo = (const float*)d_in[9];  const float* bo = (const float*)d_in[10];
    float* out = (float*)d_out;

    const int total = in_sizes[0] / Dm;
    const int Bn    = in_sizes[2] - 1;
    const int NQn   = in_sizes[1] / (Bn * Dm);
    const int Mq    = Bn * NQn;
    const float scale = rsqrtf((float)HD);

    void *pK, *pV, *pQ, *pC;
    cudaGetSymbolAddress(&pK, g_K);
    cudaGetSymbolAddress(&pV, g_V);
    cudaGetSymbolAddress(&pQ, g_Q);
    cudaGetSymbolAddress(&pC, g_ctx);

    cudaFuncSetAttribute(kv_proj_mma, cudaFuncAttributeMaxDynamicSharedMemorySize,
                         KVSM_TOTAL);

    // 1) Q projection (scale folded in)
    {
        dim3 grid((Mq + BM - 1) / BM, Dm / BN);
        sgemm_tn<<<grid, 256>>>(query, Wq, bq, nullptr, (float*)pQ, Mq, Dm, Dm, scale);
    }
    // 2+3) K & V projections via bf16 HMMA
    {
        dim3 grid((total + 127) / 128, 2);
        kv_proj_mma<<<grid, 256, KVSM_TOTAL>>>(source, Wk, bk, Wv, bv,
                                               (float*)pK, (float*)pV, total);
    }
    // 4) attention partials (HMMA flash attention)
    {
        int nsplit = (total + SPLIT_LEN - 1) / SPLIT_LEN;
        if (nsplit < 1) nsplit = 1;
        if (nsplit > MAX_SPLITS) nsplit = MAX_SPLITS;
        dim3 grid(nsplit, Hh, Bn);
        attn_partial<<<grid, 128>>>(offs, Bn, NQn);
    }
    // 5) combine (warp per (b,h,q))
    {
        int tot = Bn * Hh * NQn;
        int blocks = (tot * 32 + 255) / 256;
        attn_combine<<<blocks, 256>>>(offs, Bn, NQn);
    }
    // 6) output projection + bias + residual
    {
        dim3 grid((Mq + BM - 1) / BM, Dm / BN);
        sgemm_tn<<<grid, 256>>>((const float*)pC, Wo, bo, query, out, Mq, Dm, Dm, 1.0f);
    }
}

// round 8
// speedup vs baseline: 5.3542x; 1.2089x over previous
#include <cuda_runtime.h>
#include <cuda_bf16.h>
#include <math.h>
#include <cstdint>

// ---------------- problem constants ----------------
#define Dm 256
#define Hh 8
#define HD 32
#define NQMAX 128
#define MAXB 16
#define MAX_TOTAL 65536
#define SPLIT_LEN 512
#define MAX_SPLITS 128

// ---------------- device scratch ----------------
__device__ __nv_bfloat16 g_Kb[MAX_TOTAL * Dm];
__device__ __nv_bfloat16 g_Vb[MAX_TOTAL * Dm];
__device__ __nv_bfloat16 g_Qb[MAXB * NQMAX * Dm];
__device__ float g_ctx[MAXB * NQMAX * Dm];
__device__ float g_ctx_part[(size_t)MAXB * Hh * MAX_SPLITS * NQMAX * HD];
__device__ float g_m_part[(size_t)MAXB * Hh * MAX_SPLITS * NQMAX];
__device__ float g_l_part[(size_t)MAXB * Hh * MAX_SPLITS * NQMAX];
// pre-swizzled bf16 W for K/V proj: [matrix(2)][ntile(2)][kb(4)][row(128)][chunk(8)] x 16B
__device__ uint4 g_Wswz[2 * 2 * 4 * 128 * 8];

// ================= helpers =================
__device__ __forceinline__ uint32_t smem_to_u32(const void* p) {
    uint32_t a;
    asm("{ .reg .u64 t; cvta.to.shared.u64 t, %1; cvt.u32.u64 %0, t; }" : "=r"(a) : "l"(p));
    return a;
}
#define SMEM_SWZ(off) ((off) ^ (((off) >> 3) & 0x70))

__device__ __forceinline__ uint32_t pack_bf16x2(float a, float b) {
    uint32_t r;
    asm("cvt.rn.bf16x2.f32 %0, %1, %2;" : "=r"(r) : "f"(b), "f"(a));
    return r;
}

#define CP_ASYNC16(dst, src) \
    asm volatile("cp.async.cg.shared.global [%0], [%1], 16;" :: "r"(dst), "l"(src))
#define CP_ASYNC16_P(dst, src, sz) \
    asm volatile("cp.async.cg.shared.global [%0], [%1], 16, %2;" :: "r"(dst), "l"(src), "r"(sz))
#define CP_COMMIT() asm volatile("cp.async.commit_group;" ::: "memory")
#define CP_WAIT(n)  asm volatile("cp.async.wait_group %0;" :: "n"(n) : "memory")

// ldmatrix x4 (row-major 8x8 b16 tiles)
#define LDSM_X4(r, addr) \
    asm volatile("ldmatrix.sync.aligned.m8n8.x4.shared.b16 {%0,%1,%2,%3}, [%4];" \
        : "=r"((r)[0]), "=r"((r)[1]), "=r"((r)[2]), "=r"((r)[3]) : "r"(addr))
#define LDSM_X4_T(r, addr) \
    asm volatile("ldmatrix.sync.aligned.m8n8.x4.trans.shared.b16 {%0,%1,%2,%3}, [%4];" \
        : "=r"((r)[0]), "=r"((r)[1]), "=r"((r)[2]), "=r"((r)[3]) : "r"(addr))

// HMMA bf16: D(16x8) += A(16x16,row) * B(16x8,col)
#define MMA_BF16(d, a, b0, b1) \
    asm volatile("mma.sync.aligned.m16n8k16.row.col.f32.bf16.bf16.f32 " \
        "{%0,%1,%2,%3}, {%4,%5,%6,%7}, {%8,%9}, {%0,%1,%2,%3};" \
        : "+f"((d)[0]), "+f"((d)[1]), "+f"((d)[2]), "+f"((d)[3]) \
        : "r"((a)[0]), "r"((a)[1]), "r"((a)[2]), "r"((a)[3]), "r"(b0), "r"(b1))

// ================= W pre-swizzle (fp32 -> bf16, SW128 chunk-permuted) ======
__global__ void __launch_bounds__(256)
w_prep(const float* __restrict__ Wk, const float* __restrict__ Wv)
{
    int idx = blockIdx.x * 256 + threadIdx.x;    // 0 .. 16383
    int c   = idx & 7;
    int row = (idx >> 3) & 127;
    int kb  = (idx >> 10) & 3;
    int nt  = (idx >> 12) & 1;
    int mi  = (idx >> 13) & 1;
    const float* W = mi ? Wv : Wk;
    const float* src = W + (size_t)(nt * 128 + row) * 256 + kb * 64 + c * 8;
    float4 a = *(const float4*)src;
    float4 b = *(const float4*)(src + 4);
    uint4 u = make_uint4(pack_bf16x2(a.x, a.y), pack_bf16x2(a.z, a.w),
                         pack_bf16x2(b.x, b.y), pack_bf16x2(b.z, b.w));
    g_Wswz[(((mi * 2 + nt) * 4 + kb) * 128 + row) * 8 + (c ^ (row & 7))] = u;
}

// ================= bf16 HMMA K/V projection ==========
#define KVSM_A  0
#define KVSM_BK (4 * 128 * 128)
#define KVSM_BV (2 * 4 * 128 * 128)
#define KVSM_TOTAL (3 * 4 * 128 * 128)

__global__ void __launch_bounds__(256, 1)
kv_proj_mma(const float* __restrict__ A,
            const float* __restrict__ bkp, const float* __restrict__ bvp,
            __nv_bfloat16* __restrict__ outK, __nv_bfloat16* __restrict__ outV, int M)
{
    extern __shared__ char smem[];
    const int tid = threadIdx.x;
    const int m0 = blockIdx.x * 128;
    const int nt = blockIdx.y;
    const int n0 = nt * 128;
    const uint32_t sbase = smem_to_u32(smem);

    // ---- W tiles via cp.async from pre-swizzled bf16 (overlaps A staging) ----
    {
        const char* base = (const char*)g_Wswz;
#pragma unroll
        for (int i = 0; i < 16; i++) {
            int idx = tid + 256 * i;            // 0..4095 (K matrix)
            int kb = idx >> 10, row = (idx >> 3) & 127, c = idx & 7;
            uint32_t dst = sbase + KVSM_BK + kb * 16384 + row * 128 + c * 16;
            const char* src = base + ((((size_t)nt) * 4 + kb) * 1024 + row * 8 + c) * 16;
            CP_ASYNC16(dst, src);
        }
#pragma unroll
        for (int i = 0; i < 16; i++) {
            int idx = tid + 256 * i;            // V matrix (mi=1)
            int kb = idx >> 10, row = (idx >> 3) & 127, c = idx & 7;
            uint32_t dst = sbase + KVSM_BV + kb * 16384 + row * 128 + c * 16;
            const char* src = base + ((((size_t)(2 + nt)) * 4 + kb) * 1024 + row * 8 + c) * 16;
            CP_ASYNC16(dst, src);
        }
        CP_COMMIT();
    }

    // ---- stage A tile (128 x 256 fp32 -> bf16, SW128, 4 k-blocks) ----
#pragma unroll 4
    for (int i = 0; i < 32; i++) {
        int idx = tid + 256 * i;
        int row = idx >> 6;
        int c4  = (idx & 63) * 4;
        int gm  = m0 + row;
        float4 v = (gm < M) ? *(const float4*)(A + (size_t)gm * 256 + c4)
                            : make_float4(0.f, 0.f, 0.f, 0.f);
        int kb = c4 >> 6, kin = c4 & 63;
        uint32_t off = (uint32_t)(row * 128 + kin * 2);
        *(uint2*)(smem + KVSM_A + kb * 16384 + SMEM_SWZ(off)) =
            make_uint2(pack_bf16x2(v.x, v.y), pack_bf16x2(v.z, v.w));
    }
    CP_WAIT(0);
    __syncthreads();

    const int lane = tid & 31;
    const int wid  = tid >> 5;
    const int wm = (wid & 3) * 32;
    const int wn = (wid >> 2) * 64;

    float accK[2][8][4], accV[2][8][4];
#pragma unroll
    for (int f = 0; f < 2; f++)
#pragma unroll
        for (int g = 0; g < 8; g++)
#pragma unroll
            for (int c = 0; c < 4; c++) { accK[f][g][c] = 0.f; accV[f][g][c] = 0.f; }

    const int a_row    = wm + (lane & 15);
    const int a_kchunk = (lane >> 4) * 8;
    const int b_row    = wn + ((lane >> 4) & 1) * 8 + (lane & 7);
    const int b_kchunk = ((lane >> 3) & 1) * 8;

#pragma unroll
    for (int kb = 0; kb < 4; kb++) {
        const uint32_t aBase = sbase + KVSM_A  + kb * 16384;
        const uint32_t kBase = sbase + KVSM_BK + kb * 16384;
        const uint32_t vBase = sbase + KVSM_BV + kb * 16384;
#pragma unroll
        for (int ks = 0; ks < 4; ks++) {
            const int kk = ks * 16;
            uint32_t a0r[4], a1r[4];
            {
                uint32_t off0 = (uint32_t)( a_row       * 128 + (kk + a_kchunk) * 2);
                uint32_t off1 = (uint32_t)((a_row + 16) * 128 + (kk + a_kchunk) * 2);
                LDSM_X4(a0r, aBase + SMEM_SWZ(off0));
                LDSM_X4(a1r, aBase + SMEM_SWZ(off1));
            }
            uint32_t bkf[4][4], bvf[4][4];
#pragma unroll
            for (int p = 0; p < 4; p++) {
                uint32_t off = (uint32_t)((b_row + p * 16) * 128 + (kk + b_kchunk) * 2);
                uint32_t swz = SMEM_SWZ(off);
                LDSM_X4(bkf[p], kBase + swz);
                LDSM_X4(bvf[p], vBase + swz);
            }
#pragma unroll
            for (int p = 0; p < 4; p++) {
                MMA_BF16(accK[0][2 * p],     a0r, bkf[p][0], bkf[p][1]);
                MMA_BF16(accK[0][2 * p + 1], a0r, bkf[p][2], bkf[p][3]);
                MMA_BF16(accK[1][2 * p],     a1r, bkf[p][0], bkf[p][1]);
                MMA_BF16(accK[1][2 * p + 1], a1r, bkf[p][2], bkf[p][3]);
                MMA_BF16(accV[0][2 * p],     a0r, bvf[p][0], bvf[p][1]);
                MMA_BF16(accV[0][2 * p + 1], a0r, bvf[p][2], bvf[p][3]);
                MMA_BF16(accV[1][2 * p],     a1r, bvf[p][0], bvf[p][1]);
                MMA_BF16(accV[1][2 * p + 1], a1r, bvf[p][2], bvf[p][3]);
            }
        }
    }

    // ---- epilogue: bias + bf16 store ----
#pragma unroll
    for (int f = 0; f < 2; f++) {
        const int mA = m0 + wm + f * 16 + (lane >> 2);
        const int mB = mA + 8;
#pragma unroll
        for (int g = 0; g < 8; g++) {
            const int n = n0 + wn + g * 8 + (lane & 3) * 2;
            const float bk0 = bkp[n], bk1 = bkp[n + 1];
            const float bv0 = bvp[n], bv1 = bvp[n + 1];
            if (mA < M) {
                *(uint32_t*)(outK + (size_t)mA * 256 + n) =
                    pack_bf16x2(accK[f][g][0] + bk0, accK[f][g][1] + bk1);
                *(uint32_t*)(outV + (size_t)mA * 256 + n) =
                    pack_bf16x2(accV[f][g][0] + bv0, accV[f][g][1] + bv1);
            }
            if (mB < M) {
                *(uint32_t*)(outK + (size_t)mB * 256 + n) =
                    pack_bf16x2(accK[f][g][2] + bk0, accK[f][g][3] + bk1);
                *(uint32_t*)(outV + (size_t)mB * 256 + n) =
                    pack_bf16x2(accV[f][g][2] + bv0, accV[f][g][3] + bv1);
            }
        }
    }
}

// ================= fp32 SGEMM (Q-proj -> bf16 out, out-proj -> fp32) =======
#define BM 128
#define BN 64
#define BK 32
__global__ __launch_bounds__(256)
void sgemm_tn(const float* __restrict__ A, const float* __restrict__ W,
              const float* __restrict__ bias, const float* __restrict__ resid,
              void* __restrict__ outv, int M, int N, int K, float alpha, int obf)
{
    __shared__ float As[BK][BM + 4];
    __shared__ float Ws[BK][BN + 4];
    const int t = threadIdx.x, tx = t & 15, ty = t >> 4;
    const int m0 = blockIdx.x * BM, n0 = blockIdx.y * BN;
    float acc[8][4];
#pragma unroll
    for (int i = 0; i < 8; i++)
#pragma unroll
        for (int j = 0; j < 4; j++) acc[i][j] = 0.f;
    const int ar = t >> 3, ac = (t & 7) * 4;
    for (int k0 = 0; k0 < K; k0 += BK) {
#pragma unroll
        for (int i = 0; i < 4; i++) {
            int row = ar + 32 * i, gm = m0 + row;
            float4 v = make_float4(0.f, 0.f, 0.f, 0.f);
            if (gm < M) v = *(const float4*)(A + (size_t)gm * K + k0 + ac);
            As[ac + 0][row] = v.x; As[ac + 1][row] = v.y;
            As[ac + 2][row] = v.z; As[ac + 3][row] = v.w;
        }
#pragma unroll
        for (int i = 0; i < 2; i++) {
            int n = ar + 32 * i;
            float4 v = *(const float4*)(W + (size_t)(n0 + n) * K + k0 + ac);
            Ws[ac + 0][n] = v.x; Ws[ac + 1][n] = v.y;
            Ws[ac + 2][n] = v.z; Ws[ac + 3][n] = v.w;
        }
        __syncthreads();
#pragma unroll
        for (int kk = 0; kk < BK; kk++) {
            float a[8], w[4];
#pragma unroll
            for (int i = 0; i < 8; i++) a[i] = As[kk][ty * 8 + i];
#pragma unroll
            for (int j = 0; j < 4; j++) w[j] = Ws[kk][tx * 4 + j];
#pragma unroll
            for (int i = 0; i < 8; i++)
#pragma unroll
                for (int j = 0; j < 4; j++) acc[i][j] = fmaf(a[i], w[j], acc[i][j]);
        }
        __syncthreads();
    }
#pragma unroll
    for (int i = 0; i < 8; i++) {
        int gm = m0 + ty * 8 + i;
        if (gm >= M) continue;
#pragma unroll
        for (int j = 0; j < 4; j++) {
            int gn = n0 + tx * 4 + j;
            float v = acc[i][j];
            if (bias) v += bias[gn];
            v *= alpha;
            if (resid) v += resid[(size_t)gm * N + gn];
            if (obf) ((__nv_bfloat16*)outv)[(size_t)gm * N + gn] = __float2bfloat16(v);
            else     ((float*)outv)[(size_t)gm * N + gn] = v;
        }
    }
}

// ================= HMMA flash-attention partials (cp.async pipelined) ======
#define TK 64
#define KROWB 80       /* smem row stride bytes: conflict-free ldmatrix */
#define STG_B 10240    /* per-stage bytes: K(64*80) + V(64*80) */
#define NSTG 3

__global__ void __launch_bounds__(128, 2)
attn_partial(const int* __restrict__ offs, int Bn, int NQn)
{
    const int s = blockIdx.x, h = blockIdx.y, b = blockIdx.z;
    const int tid = threadIdx.x;
    const int lane = tid & 31, wid = tid >> 5;
    const int beg = offs[b];
    const int len = offs[b + 1] - beg;
    const int k0  = s * SPLIT_LEN;
    if (k0 >= len) return;
    const int kend = min(k0 + SPLIT_LEN, len);

    __shared__ __align__(16) char sAll[NSTG * STG_B];
    const uint32_t sbase = smem_to_u32(sAll);

    const int wm = wid * 32;

    // ---- Q fragments from bf16 g_Qb (scale folded at projection) ----
    uint32_t qa[2][2][4];
#pragma unroll
    for (int f = 0; f < 2; f++)
#pragma unroll
        for (int c = 0; c < 2; c++) {
            const int col = h * HD + c * 16 + 2 * (lane & 3);
#pragma unroll
            for (int e = 0; e < 4; e++) {
                int row = wm + 16 * f + (lane >> 2) + (e & 1) * 8;
                int cc  = col + (e >> 1) * 8;
                qa[f][c][e] = (row < NQn)
                    ? *(const uint32_t*)(g_Qb + ((size_t)(b * NQn + row)) * Dm + cc) : 0u;
            }
        }

    float o[2][4][4];
#pragma unroll
    for (int f = 0; f < 2; f++)
#pragma unroll
        for (int j = 0; j < 4; j++)
#pragma unroll
            for (int e = 0; e < 4; e++) o[f][j][e] = 0.f;
    float mrow[2][2], lrow[2][2];
#pragma unroll
    for (int f = 0; f < 2; f++) { mrow[f][0] = mrow[f][1] = -1e30f; lrow[f][0] = lrow[f][1] = 0.f; }

    const int grp = lane >> 3, lr = lane & 7;
    const int nch = (kend - k0 + TK - 1) / TK;

    // issue stage ci into buffer
    auto issue = [&](int ci) {
        const int buf = ci % NSTG;
        const int ktl = k0 + ci * TK;
        const int nv2 = min(TK, kend - ktl);
        const uint32_t sK = sbase + buf * STG_B;
        const uint32_t sV = sK + 5120;
#pragma unroll
        for (int i = 0; i < 2; i++) {
            int idx = tid + 128 * i;           // 256 chunks
            int row = idx >> 2, c = idx & 3;
            int ok = row < nv2;
            int rr = ok ? row : 0;
            const char* srcK = (const char*)(g_Kb + ((size_t)(beg + ktl + rr)) * Dm + h * HD) + c * 16;
            const char* srcV = (const char*)(g_Vb + ((size_t)(beg + ktl + rr)) * Dm + h * HD) + c * 16;
            int sz = ok ? 16 : 0;
            CP_ASYNC16_P(sK + row * KROWB + c * 16, srcK, sz);
            CP_ASYNC16_P(sV + row * KROWB + c * 16, srcV, sz);
        }
        CP_COMMIT();
    };

    issue(0);
    for (int ci = 0; ci < nch; ci++) {
        if (ci + 1 < nch) { issue(ci + 1); CP_WAIT(1); }
        else             { CP_WAIT(0); }
        __syncthreads();

        const int buf = ci % NSTG;
        const uint32_t sK = sbase + buf * STG_B;
        const uint32_t sV = sK + 5120;
        const int nv = min(TK, kend - (k0 + ci * TK));

        // ---- S = Q @ K^T ----
        float sc[2][8][4];
#pragma unroll
        for (int f = 0; f < 2; f++)
#pragma unroll
            for (int ntl = 0; ntl < 8; ntl++)
#pragma unroll
                for (int e = 0; e < 4; e++) sc[f][ntl][e] = 0.f;

#pragma unroll
        for (int c = 0; c < 2; c++) {
#pragma unroll
            for (int p = 0; p < 4; p++) {
                int krow = p * 16 + (grp >> 1) * 8 + lr;
                int hdo  = c * 16 + (grp & 1) * 8;
                uint32_t kb[4];
                LDSM_X4(kb, sK + krow * KROWB + hdo * 2);
#pragma unroll
                for (int f = 0; f < 2; f++) {
                    MMA_BF16(sc[f][2 * p],     qa[f][c], kb[0], kb[1]);
                    MMA_BF16(sc[f][2 * p + 1], qa[f][c], kb[2], kb[3]);
                }
            }
        }

        // ---- mask padded keys (tail chunk only) ----
        if (nv < TK) {
#pragma unroll
            for (int ntl = 0; ntl < 8; ntl++) {
                int c0 = ntl * 8 + 2 * (lane & 3);
#pragma unroll
                for (int f = 0; f < 2; f++) {
                    if (c0     >= nv) { sc[f][ntl][0] = -3e30f; sc[f][ntl][2] = -3e30f; }
                    if (c0 + 1 >= nv) { sc[f][ntl][1] = -3e30f; sc[f][ntl][3] = -3e30f; }
                }
            }
        }

        // ---- online softmax ----
#pragma unroll
        for (int f = 0; f < 2; f++) {
#pragma unroll
            for (int half = 0; half < 2; half++) {
                float mx = -3e30f;
#pragma unroll
                for (int ntl = 0; ntl < 8; ntl++)
                    mx = fmaxf(mx, fmaxf(sc[f][ntl][2 * half], sc[f][ntl][2 * half + 1]));
                mx = fmaxf(mx, __shfl_xor_sync(0xffffffffu, mx, 1));
                mx = fmaxf(mx, __shfl_xor_sync(0xffffffffu, mx, 2));
                float mnew = fmaxf(mrow[f][half], mx);
                float corr = __expf(mrow[f][half] - mnew);
                mrow[f][half] = mnew;
                lrow[f][half] *= corr;
#pragma unroll
                for (int j = 0; j < 4; j++) {
                    o[f][j][2 * half]     *= corr;
                    o[f][j][2 * half + 1] *= corr;
                }
                float rs = 0.f;
#pragma unroll
                for (int ntl = 0; ntl < 8; ntl++) {
                    float p0 = __expf(sc[f][ntl][2 * half]     - mnew);
                    float p1 = __expf(sc[f][ntl][2 * half + 1] - mnew);
                    sc[f][ntl][2 * half] = p0; sc[f][ntl][2 * half + 1] = p1;
                    rs += p0 + p1;
                }
                rs += __shfl_xor_sync(0xffffffffu, rs, 1);
                rs += __shfl_xor_sync(0xffffffffu, rs, 2);
                lrow[f][half] += rs;
            }
        }

        // ---- P -> bf16 A-frags ----
        uint32_t pa[2][4][4];
#pragma unroll
        for (int f = 0; f < 2; f++)
#pragma unroll
            for (int kc = 0; kc < 4; kc++) {
                pa[f][kc][0] = pack_bf16x2(sc[f][2 * kc][0],     sc[f][2 * kc][1]);
                pa[f][kc][1] = pack_bf16x2(sc[f][2 * kc][2],     sc[f][2 * kc][3]);
                pa[f][kc][2] = pack_bf16x2(sc[f][2 * kc + 1][0], sc[f][2 * kc + 1][1]);
                pa[f][kc][3] = pack_bf16x2(sc[f][2 * kc + 1][2], sc[f][2 * kc + 1][3]);
            }

        // ---- ctx += P @ V ----
#pragma unroll
        for (int kc = 0; kc < 4; kc++) {
#pragma unroll
            for (int vt = 0; vt < 2; vt++) {
                int krow = kc * 16 + (grp & 1) * 8 + lr;
                int hdo  = vt * 16 + (grp >> 1) * 8;
                uint32_t vb[4];
                LDSM_X4_T(vb, sV + krow * KROWB + hdo * 2);
#pragma unroll
                for (int f = 0; f < 2; f++) {
                    MMA_BF16(o[f][2 * vt],     pa[f][kc], vb[0], vb[1]);
                    MMA_BF16(o[f][2 * vt + 1], pa[f][kc], vb[2], vb[3]);
                }
            }
        }
    }

    // ---- write partials ----
    const size_t pbase = ((size_t)(b * Hh + h) * MAX_SPLITS + s);
#pragma unroll
    for (int f = 0; f < 2; f++)
#pragma unroll
        for (int half = 0; half < 2; half++) {
            int row = wm + 16 * f + 8 * half + (lane >> 2);
            if (row < NQn) {
                if ((lane & 3) == 0) {
                    g_m_part[pbase * NQMAX + row] = mrow[f][half];
                    g_l_part[pbase * NQMAX + row] = lrow[f][half];
                }
#pragma unroll
                for (int j = 0; j < 4; j++) {
                    int d = j * 8 + 2 * (lane & 3);
                    *(float2*)(g_ctx_part + (pbase * NQMAX + row) * HD + d) =
                        make_float2(o[f][j][2 * half], o[f][j][2 * half + 1]);
                }
            }
        }
}

// ================= combine split partials (warp per (b,h,q)) ==============
__global__ __launch_bounds__(256)
void attn_combine(const int* __restrict__ offs, int Bn, int NQn)
{
    const int gwarp = (blockIdx.x * blockDim.x + threadIdx.x) >> 5;
    const int lane  = threadIdx.x & 31;
    const int tot = Bn * Hh * NQn;
    if (gwarp >= tot) return;
    const int q  = gwarp % NQn;
    const int bh = gwarp / NQn;
    const int b  = bh / Hh, h = bh % Hh;

    const int len = offs[b + 1] - offs[b];
    int ns = (len > 0) ? min((len + SPLIT_LEN - 1) / SPLIT_LEN, MAX_SPLITS) : 0;

    const size_t base = (size_t)bh * MAX_SPLITS;
    float M = -1e30f;
    for (int s2 = lane; s2 < ns; s2 += 32)
        M = fmaxf(M, g_m_part[(base + s2) * NQMAX + q]);
#pragma unroll
    for (int od = 16; od; od >>= 1) M = fmaxf(M, __shfl_xor_sync(0xffffffffu, M, od));

    float L = 0.f;
    for (int s2 = lane; s2 < ns; s2 += 32)
        L += __expf(g_m_part[(base + s2) * NQMAX + q] - M) * g_l_part[(base + s2) * NQMAX + q];
#pragma unroll
    for (int od = 16; od; od >>= 1) L += __shfl_xor_sync(0xffffffffu, L, od);

    float ctx = 0.f;
    for (int s2 = 0; s2 < ns; s2++) {
        float w = __expf(g_m_part[(base + s2) * NQMAX + q] - M);
        ctx += w * g_ctx_part[((base + s2) * NQMAX + q) * HD + lane];
    }
    float inv = (ns > 0 && L > 0.f) ? 1.f / L : 0.f;
    g_ctx[((size_t)b * NQn + q) * Dm + h * HD + lane] = ctx * inv;
}

// ================= launch =================
extern "C" void kernel_launch(void* const* d_in, const int* in_sizes, int n_in,
                              void* d_out, int out_size)
{
    const float* source = (const float*)d_in[0];
    const float* query  = (const float*)d_in[1];
    const int*   offs   = (const int*)  d_in[2];
    const float* Wq = (const float*)d_in[3];  const float* bq = (const float*)d_in[4];
    const float* Wk = (const float*)d_in[5];  const float* bk = (const float*)d_in[6];
    const float* Wv = (const float*)d_in[7];  const float* bv = (const float*)d_in[8];
    const float* Wo = (const float*)d_in[9];  const float* bo = (const float*)d_in[10];
    float* out = (float*)d_out;

    const int total = in_sizes[0] / Dm;
    const int Bn    = in_sizes[2] - 1;
    const int NQn   = in_sizes[1] / (Bn * Dm);
    const int Mq    = Bn * NQn;
    const float scale = rsqrtf((float)HD);

    void *pK, *pV, *pQ, *pC;
    cudaGetSymbolAddress(&pK, g_Kb);
    cudaGetSymbolAddress(&pV, g_Vb);
    cudaGetSymbolAddress(&pQ, g_Qb);
    cudaGetSymbolAddress(&pC, g_ctx);

    cudaFuncSetAttribute(kv_proj_mma, cudaFuncAttributeMaxDynamicSharedMemorySize,
                         KVSM_TOTAL);

    // 0) pre-swizzle Wk/Wv to bf16 swizzled layout
    w_prep<<<64, 256>>>(Wk, Wv);

    // 1) Q projection -> bf16 (scale folded in)
    {
        dim3 grid((Mq + BM - 1) / BM, Dm / BN);
        sgemm_tn<<<grid, 256>>>(query, Wq, bq, nullptr, pQ, Mq, Dm, Dm, scale, 1);
    }
    // 2+3) K & V projections via bf16 HMMA, bf16 outputs
    {
        dim3 grid((total + 127) / 128, 2);
        kv_proj_mma<<<grid, 256, KVSM_TOTAL>>>(source, bk, bv,
                                               (__nv_bfloat16*)pK, (__nv_bfloat16*)pV, total);
    }
    // 4) attention partials (HMMA flash attention, cp.async pipelined)
    {
        int nsplit = (total + SPLIT_LEN - 1) / SPLIT_LEN;
        if (nsplit < 1) nsplit = 1;
        if (nsplit > MAX_SPLITS) nsplit = MAX_SPLITS;
        dim3 grid(nsplit, Hh, Bn);
        attn_partial<<<grid, 128>>>(offs, Bn, NQn);
    }
    // 5) combine
    {
        int tot = Bn * Hh * NQn;
        int blocks = (tot * 32 + 255) / 256;
        attn_combine<<<blocks, 256>>>(offs, Bn, NQn);
    }
    // 6) output projection + bias + residual (fp32)
    {
        dim3 grid((Mq + BM - 1) / BM, Dm / BN);
        sgemm_tn<<<grid, 256>>>((const float*)pC, Wo, bo, query, out, Mq, Dm, Dm, 1.0f, 0);
    }
}

// round 11
// speedup vs baseline: 5.9298x; 1.1075x over previous
#include <cuda_runtime.h>
#include <cuda_bf16.h>
#include <math.h>
#include <cstdint>

// ---------------- problem constants ----------------
#define Dm 256
#define Hh 8
#define HD 32
#define NQMAX 128
#define MAXB 16
#define MAX_TOTAL 65536
#define SPLIT_LEN 2048
#define MAX_SPLITS 32

// ---------------- device scratch ----------------
__device__ __nv_bfloat16 g_Kb[MAX_TOTAL * Dm];
__device__ __nv_bfloat16 g_Vb[MAX_TOTAL * Dm];
__device__ __nv_bfloat16 g_Qb[MAXB * NQMAX * Dm];
__device__ float g_ctx[MAXB * NQMAX * Dm];
__device__ float g_ctx_part[(size_t)MAXB * Hh * MAX_SPLITS * NQMAX * HD];
__device__ float g_m_part[(size_t)MAXB * Hh * MAX_SPLITS * NQMAX];
__device__ float g_l_part[(size_t)MAXB * Hh * MAX_SPLITS * NQMAX];
// pre-swizzled bf16 W for K/V proj: [matrix(2)][ntile(2)][kb(4)][row(128)][chunk(8)] x 16B
__device__ uint4 g_Wswz[2 * 2 * 4 * 128 * 8];
// pre-swizzled bf16 source: [kb(4)][token(MAX_TOTAL)][chunk(8)] x 16B  (32 MB)
__device__ uint4 g_Sswz[(size_t)4 * MAX_TOTAL * 8];

// ================= helpers =================
__device__ __forceinline__ uint32_t smem_to_u32(const void* p) {
    uint32_t a;
    asm("{ .reg .u64 t; cvta.to.shared.u64 t, %1; cvt.u32.u64 %0, t; }" : "=r"(a) : "l"(p));
    return a;
}
#define SMEM_SWZ(off) ((off) ^ (((off) >> 3) & 0x70))

__device__ __forceinline__ uint32_t pack_bf16x2(float a, float b) {
    uint32_t r;
    asm("cvt.rn.bf16x2.f32 %0, %1, %2;" : "=r"(r) : "f"(b), "f"(a));
    return r;
}

#define CP_ASYNC16(dst, src) \
    asm volatile("cp.async.cg.shared.global [%0], [%1], 16;" :: "r"(dst), "l"(src))
#define CP_ASYNC16_P(dst, src, sz) \
    asm volatile("cp.async.cg.shared.global [%0], [%1], 16, %2;" :: "r"(dst), "l"(src), "r"(sz))
#define CP_COMMIT() asm volatile("cp.async.commit_group;" ::: "memory")
#define CP_WAIT(n)  asm volatile("cp.async.wait_group %0;" :: "n"(n) : "memory")

// ldmatrix x4 (row-major 8x8 b16 tiles)
#define LDSM_X4(r, addr) \
    asm volatile("ldmatrix.sync.aligned.m8n8.x4.shared.b16 {%0,%1,%2,%3}, [%4];" \
        : "=r"((r)[0]), "=r"((r)[1]), "=r"((r)[2]), "=r"((r)[3]) : "r"(addr))
#define LDSM_X4_T(r, addr) \
    asm volatile("ldmatrix.sync.aligned.m8n8.x4.trans.shared.b16 {%0,%1,%2,%3}, [%4];" \
        : "=r"((r)[0]), "=r"((r)[1]), "=r"((r)[2]), "=r"((r)[3]) : "r"(addr))

// HMMA bf16: D(16x8) += A(16x16,row) * B(16x8,col)
#define MMA_BF16(d, a, b0, b1) \
    asm volatile("mma.sync.aligned.m16n8k16.row.col.f32.bf16.bf16.f32 " \
        "{%0,%1,%2,%3}, {%4,%5,%6,%7}, {%8,%9}, {%0,%1,%2,%3};" \
        : "+f"((d)[0]), "+f"((d)[1]), "+f"((d)[2]), "+f"((d)[3]) \
        : "r"((a)[0]), "r"((a)[1]), "r"((a)[2]), "r"((a)[3]), "r"(b0), "r"(b1))

// ================= W pre-swizzle (fp32 -> bf16, SW128 chunk-permuted) ======
__global__ void __launch_bounds__(256)
w_prep(const float* __restrict__ Wk, const float* __restrict__ Wv)
{
    int idx = blockIdx.x * 256 + threadIdx.x;    // 0 .. 16383
    int c   = idx & 7;
    int row = (idx >> 3) & 127;
    int kb  = (idx >> 10) & 3;
    int nt  = (idx >> 12) & 1;
    int mi  = (idx >> 13) & 1;
    const float* W = mi ? Wv : Wk;
    const float* src = W + (size_t)(nt * 128 + row) * 256 + kb * 64 + c * 8;
    float4 a = *(const float4*)src;
    float4 b = *(const float4*)(src + 4);
    uint4 u = make_uint4(pack_bf16x2(a.x, a.y), pack_bf16x2(a.z, a.w),
                         pack_bf16x2(b.x, b.y), pack_bf16x2(b.z, b.w));
    g_Wswz[(((mi * 2 + nt) * 4 + kb) * 128 + row) * 8 + (c ^ (row & 7))] = u;
}

// ================= source pre-swizzle (fp32 -> bf16, chunk-permuted) =======
__global__ void __launch_bounds__(256)
src_prep(const float* __restrict__ S, int total)
{
    int idx = blockIdx.x * 256 + threadIdx.x;    // chunk id
    if (idx >= total * 32) return;
    int c     = idx & 7;
    int kb    = (idx >> 3) & 3;
    int token = idx >> 5;
    const float* src = S + (size_t)token * 256 + kb * 64 + c * 8;
    float4 a = *(const float4*)src;
    float4 b = *(const float4*)(src + 4);
    uint4 u = make_uint4(pack_bf16x2(a.x, a.y), pack_bf16x2(a.z, a.w),
                         pack_bf16x2(b.x, b.y), pack_bf16x2(b.z, b.w));
    g_Sswz[((size_t)kb * MAX_TOTAL + token) * 8 + (c ^ (token & 7))] = u;
}

// ================= bf16 HMMA K/V projection ==========
#define KVSM_A  0
#define KVSM_BK (4 * 128 * 128)
#define KVSM_BV (2 * 4 * 128 * 128)
#define KVSM_TOTAL (3 * 4 * 128 * 128)

__global__ void __launch_bounds__(256, 1)
kv_proj_mma(const float* __restrict__ bkp, const float* __restrict__ bvp,
            __nv_bfloat16* __restrict__ outK, __nv_bfloat16* __restrict__ outV, int M)
{
    extern __shared__ char smem[];
    const int tid = threadIdx.x;
    const int m0 = blockIdx.x * 128;
    const int nt = blockIdx.y;
    const int n0 = nt * 128;
    const uint32_t sbase = smem_to_u32(smem);

    // ---- group 0: W tiles (both matrices) + A kb0 ----
    {
        const char* base = (const char*)g_Wswz;
#pragma unroll
        for (int i = 0; i < 16; i++) {
            int idx = tid + 256 * i;            // K matrix
            int kb = idx >> 10, row = (idx >> 3) & 127, c = idx & 7;
            uint32_t dst = sbase + KVSM_BK + kb * 16384 + row * 128 + c * 16;
            const char* src = base + ((((size_t)nt) * 4 + kb) * 1024 + row * 8 + c) * 16;
            CP_ASYNC16(dst, src);
        }
#pragma unroll
        for (int i = 0; i < 16; i++) {
            int idx = tid + 256 * i;            // V matrix
            int kb = idx >> 10, row = (idx >> 3) & 127, c = idx & 7;
            uint32_t dst = sbase + KVSM_BV + kb * 16384 + row * 128 + c * 16;
            const char* src = base + ((((size_t)(2 + nt)) * 4 + kb) * 1024 + row * 8 + c) * 16;
            CP_ASYNC16(dst, src);
        }
    }
    // A kb blocks via cp.async from pre-swizzled bf16 source (zero-fill OOB)
    auto issueA = [&](int kb) {
        const char* base = (const char*)g_Sswz;
#pragma unroll
        for (int i = 0; i < 4; i++) {
            int idx = tid + 256 * i;            // 1024 chunks
            int row = idx >> 3, c = idx & 7;
            int gm = m0 + row;
            int ok = gm < M;
            int rr = ok ? gm : 0;
            uint32_t dst = sbase + KVSM_A + kb * 16384 + row * 128 + c * 16;
            const char* src = base + (((size_t)kb * MAX_TOTAL + rr) * 8 + c) * 16;
            CP_ASYNC16_P(dst, src, ok ? 16 : 0);
        }
    };
    issueA(0); CP_COMMIT();
    issueA(1); CP_COMMIT();
    issueA(2); CP_COMMIT();
    issueA(3); CP_COMMIT();

    const int lane = tid & 31;
    const int wid  = tid >> 5;
    const int wm = (wid & 3) * 32;
    const int wn = (wid >> 2) * 64;

    float accK[2][8][4], accV[2][8][4];
#pragma unroll
    for (int f = 0; f < 2; f++)
#pragma unroll
        for (int g = 0; g < 8; g++)
#pragma unroll
            for (int c = 0; c < 4; c++) { accK[f][g][c] = 0.f; accV[f][g][c] = 0.f; }

    const int a_row    = wm + (lane & 15);
    const int a_kchunk = (lane >> 4) * 8;
    const int b_row    = wn + ((lane >> 4) & 1) * 8 + (lane & 7);
    const int b_kchunk = ((lane >> 3) & 1) * 8;

    auto compute_kb = [&](int kb) {
        const uint32_t aBase = sbase + KVSM_A  + kb * 16384;
        const uint32_t kBase = sbase + KVSM_BK + kb * 16384;
        const uint32_t vBase = sbase + KVSM_BV + kb * 16384;
#pragma unroll
        for (int ks = 0; ks < 4; ks++) {
            const int kk = ks * 16;
            uint32_t a0r[4], a1r[4];
            {
                uint32_t off0 = (uint32_t)( a_row       * 128 + (kk + a_kchunk) * 2);
                uint32_t off1 = (uint32_t)((a_row + 16) * 128 + (kk + a_kchunk) * 2);
                LDSM_X4(a0r, aBase + SMEM_SWZ(off0));
                LDSM_X4(a1r, aBase + SMEM_SWZ(off1));
            }
            uint32_t bkf[4][4], bvf[4][4];
#pragma unroll
            for (int p = 0; p < 4; p++) {
                uint32_t off = (uint32_t)((b_row + p * 16) * 128 + (kk + b_kchunk) * 2);
                uint32_t swz = SMEM_SWZ(off);
                LDSM_X4(bkf[p], kBase + swz);
                LDSM_X4(bvf[p], vBase + swz);
            }
#pragma unroll
            for (int p = 0; p < 4; p++) {
                MMA_BF16(accK[0][2 * p],     a0r, bkf[p][0], bkf[p][1]);
                MMA_BF16(accK[0][2 * p + 1], a0r, bkf[p][2], bkf[p][3]);
                MMA_BF16(accK[1][2 * p],     a1r, bkf[p][0], bkf[p][1]);
                MMA_BF16(accK[1][2 * p + 1], a1r, bkf[p][2], bkf[p][3]);
                MMA_BF16(accV[0][2 * p],     a0r, bvf[p][0], bvf[p][1]);
                MMA_BF16(accV[0][2 * p + 1], a0r, bvf[p][2], bvf[p][3]);
                MMA_BF16(accV[1][2 * p],     a1r, bvf[p][0], bvf[p][1]);
                MMA_BF16(accV[1][2 * p + 1], a1r, bvf[p][2], bvf[p][3]);
            }
        }
    };

    // staircase: W+A0 ready -> compute kb0 while A1..A3 land
    CP_WAIT(3); __syncthreads(); compute_kb(0);
    CP_WAIT(2); __syncthreads(); compute_kb(1);
    CP_WAIT(1); __syncthreads(); compute_kb(2);
    CP_WAIT(0); __syncthreads(); compute_kb(3);

    // ---- epilogue: bias + bf16 store ----
#pragma unroll
    for (int f = 0; f < 2; f++) {
        const int mA = m0 + wm + f * 16 + (lane >> 2);
        const int mB = mA + 8;
#pragma unroll
        for (int g = 0; g < 8; g++) {
            const int n = n0 + wn + g * 8 + (lane & 3) * 2;
            const float bk0 = bkp[n], bk1 = bkp[n + 1];
            const float bv0 = bvp[n], bv1 = bvp[n + 1];
            if (mA < M) {
                *(uint32_t*)(outK + (size_t)mA * 256 + n) =
                    pack_bf16x2(accK[f][g][0] + bk0, accK[f][g][1] + bk1);
                *(uint32_t*)(outV + (size_t)mA * 256 + n) =
                    pack_bf16x2(accV[f][g][0] + bv0, accV[f][g][1] + bv1);
            }
            if (mB < M) {
                *(uint32_t*)(outK + (size_t)mB * 256 + n) =
                    pack_bf16x2(accK[f][g][2] + bk0, accK[f][g][3] + bk1);
                *(uint32_t*)(outV + (size_t)mB * 256 + n) =
                    pack_bf16x2(accV[f][g][2] + bv0, accV[f][g][3] + bv1);
            }
        }
    }
}

// ================= fp32 SGEMM (Q-proj -> bf16 out, out-proj -> fp32) =======
#define BM 128
#define BN 64
#define BK 32
__global__ __launch_bounds__(256)
void sgemm_tn(const float* __restrict__ A, const float* __restrict__ W,
              const float* __restrict__ bias, const float* __restrict__ resid,
              void* __restrict__ outv, int M, int N, int K, float alpha, int obf)
{
    __shared__ float As[BK][BM + 4];
    __shared__ float Ws[BK][BN + 4];
    const int t = threadIdx.x, tx = t & 15, ty = t >> 4;
    const int m0 = blockIdx.x * BM, n0 = blockIdx.y * BN;
    float acc[8][4];
#pragma unroll
    for (int i = 0; i < 8; i++)
#pragma unroll
        for (int j = 0; j < 4; j++) acc[i][j] = 0.f;
    const int ar = t >> 3, ac = (t & 7) * 4;
    for (int k0 = 0; k0 < K; k0 += BK) {
#pragma unroll
        for (int i = 0; i < 4; i++) {
            int row = ar + 32 * i, gm = m0 + row;
            float4 v = make_float4(0.f, 0.f, 0.f, 0.f);
            if (gm < M) v = *(const float4*)(A + (size_t)gm * K + k0 + ac);
            As[ac + 0][row] = v.x; As[ac + 1][row] = v.y;
            As[ac + 2][row] = v.z; As[ac + 3][row] = v.w;
        }
#pragma unroll
        for (int i = 0; i < 2; i++) {
            int n = ar + 32 * i;
            float4 v = *(const float4*)(W + (size_t)(n0 + n) * K + k0 + ac);
            Ws[ac + 0][n] = v.x; Ws[ac + 1][n] = v.y;
            Ws[ac + 2][n] = v.z; Ws[ac + 3][n] = v.w;
        }
        __syncthreads();
#pragma unroll
        for (int kk = 0; kk < BK; kk++) {
            float a[8], w[4];
#pragma unroll
            for (int i = 0; i < 8; i++) a[i] = As[kk][ty * 8 + i];
#pragma unroll
            for (int j = 0; j < 4; j++) w[j] = Ws[kk][tx * 4 + j];
#pragma unroll
            for (int i = 0; i < 8; i++)
#pragma unroll
                for (int j = 0; j < 4; j++) acc[i][j] = fmaf(a[i], w[j], acc[i][j]);
        }
        __syncthreads();
    }
#pragma unroll
    for (int i = 0; i < 8; i++) {
        int gm = m0 + ty * 8 + i;
        if (gm >= M) continue;
#pragma unroll
        for (int j = 0; j < 4; j++) {
            int gn = n0 + tx * 4 + j;
            float v = acc[i][j];
            if (bias) v += bias[gn];
            v *= alpha;
            if (resid) v += resid[(size_t)gm * N + gn];
            if (obf) ((__nv_bfloat16*)outv)[(size_t)gm * N + gn] = __float2bfloat16(v);
            else     ((float*)outv)[(size_t)gm * N + gn] = v;
        }
    }
}

// ================= HMMA flash-attention partials (cp.async pipelined) ======
#define TK 64
#define KROWB 80       /* smem row stride bytes: conflict-free ldmatrix */
#define STG_B 10240    /* per-stage bytes: K(64*80) + V(64*80) */
#define NSTG 3

__global__ void __launch_bounds__(128, 2)
attn_partial(const int* __restrict__ offs, int Bn, int NQn)
{
    const int s = blockIdx.x, h = blockIdx.y, b = blockIdx.z;
    const int tid = threadIdx.x;
    const int lane = tid & 31, wid = tid >> 5;
    const int beg = offs[b];
    const int len = offs[b + 1] - beg;
    const int k0  = s * SPLIT_LEN;
    if (k0 >= len) return;
    const int kend = min(k0 + SPLIT_LEN, len);

    __shared__ __align__(16) char sAll[NSTG * STG_B];
    const uint32_t sbase = smem_to_u32(sAll);

    const int wm = wid * 32;

    // ---- Q fragments from bf16 g_Qb (scale folded at projection) ----
    uint32_t qa[2][2][4];
#pragma unroll
    for (int f = 0; f < 2; f++)
#pragma unroll
        for (int c = 0; c < 2; c++) {
            const int col = h * HD + c * 16 + 2 * (lane & 3);
#pragma unroll
            for (int e = 0; e < 4; e++) {
                int row = wm + 16 * f + (lane >> 2) + (e & 1) * 8;
                int cc  = col + (e >> 1) * 8;
                qa[f][c][e] = (row < NQn)
                    ? *(const uint32_t*)(g_Qb + ((size_t)(b * NQn + row)) * Dm + cc) : 0u;
            }
        }

    float o[2][4][4];
#pragma unroll
    for (int f = 0; f < 2; f++)
#pragma unroll
        for (int j = 0; j < 4; j++)
#pragma unroll
            for (int e = 0; e < 4; e++) o[f][j][e] = 0.f;
    float mrow[2][2], lrow[2][2];
#pragma unroll
    for (int f = 0; f < 2; f++) { mrow[f][0] = mrow[f][1] = -1e30f; lrow[f][0] = lrow[f][1] = 0.f; }

    const int grp = lane >> 3, lr = lane & 7;
    const int nch = (kend - k0 + TK - 1) / TK;

    auto issue = [&](int ci) {
        const int buf = ci % NSTG;
        const int ktl = k0 + ci * TK;
        const int nv2 = min(TK, kend - ktl);
        const uint32_t sK = sbase + buf * STG_B;
        const uint32_t sV = sK + 5120;
#pragma unroll
        for (int i = 0; i < 2; i++) {
            int idx = tid + 128 * i;
            int row = idx >> 2, c = idx & 3;
            int ok = row < nv2;
            int rr = ok ? row : 0;
            const char* srcK = (const char*)(g_Kb + ((size_t)(beg + ktl + rr)) * Dm + h * HD) + c * 16;
            const char* srcV = (const char*)(g_Vb + ((size_t)(beg + ktl + rr)) * Dm + h * HD) + c * 16;
            int sz = ok ? 16 : 0;
            CP_ASYNC16_P(sK + row * KROWB + c * 16, srcK, sz);
            CP_ASYNC16_P(sV + row * KROWB + c * 16, srcV, sz);
        }
        CP_COMMIT();
    };

    issue(0);
    if (nch > 1) issue(1);
    for (int ci = 0; ci < nch; ci++) {
        if (ci + 2 < nch) { issue(ci + 2); CP_WAIT(2); }
        else if (ci + 1 < nch) CP_WAIT(1);
        else CP_WAIT(0);
        __syncthreads();

        const int buf = ci % NSTG;
        const uint32_t sK = sbase + buf * STG_B;
        const uint32_t sV = sK + 5120;
        const int nv = min(TK, kend - (k0 + ci * TK));

        // ---- S = Q @ K^T ----
        float sc[2][8][4];
#pragma unroll
        for (int f = 0; f < 2; f++)
#pragma unroll
            for (int ntl = 0; ntl < 8; ntl++)
#pragma unroll
                for (int e = 0; e < 4; e++) sc[f][ntl][e] = 0.f;

#pragma unroll
        for (int c = 0; c < 2; c++) {
#pragma unroll
            for (int p = 0; p < 4; p++) {
                int krow = p * 16 + (grp >> 1) * 8 + lr;
                int hdo  = c * 16 + (grp & 1) * 8;
                uint32_t kb[4];
                LDSM_X4(kb, sK + krow * KROWB + hdo * 2);
#pragma unroll
                for (int f = 0; f < 2; f++) {
                    MMA_BF16(sc[f][2 * p],     qa[f][c], kb[0], kb[1]);
                    MMA_BF16(sc[f][2 * p + 1], qa[f][c], kb[2], kb[3]);
                }
            }
        }

        if (nv < TK) {
#pragma unroll
            for (int ntl = 0; ntl < 8; ntl++) {
                int c0 = ntl * 8 + 2 * (lane & 3);
#pragma unroll
                for (int f = 0; f < 2; f++) {
                    if (c0     >= nv) { sc[f][ntl][0] = -3e30f; sc[f][ntl][2] = -3e30f; }
                    if (c0 + 1 >= nv) { sc[f][ntl][1] = -3e30f; sc[f][ntl][3] = -3e30f; }
                }
            }
        }

        // ---- online softmax ----
#pragma unroll
        for (int f = 0; f < 2; f++) {
#pragma unroll
            for (int half = 0; half < 2; half++) {
                float mx = -3e30f;
#pragma unroll
                for (int ntl = 0; ntl < 8; ntl++)
                    mx = fmaxf(mx, fmaxf(sc[f][ntl][2 * half], sc[f][ntl][2 * half + 1]));
                mx = fmaxf(mx, __shfl_xor_sync(0xffffffffu, mx, 1));
                mx = fmaxf(mx, __shfl_xor_sync(0xffffffffu, mx, 2));
                float mnew = fmaxf(mrow[f][half], mx);
                float corr = __expf(mrow[f][half] - mnew);
                mrow[f][half] = mnew;
                lrow[f][half] *= corr;
#pragma unroll
                for (int j = 0; j < 4; j++) {
                    o[f][j][2 * half]     *= corr;
                    o[f][j][2 * half + 1] *= corr;
                }
                float rs = 0.f;
#pragma unroll
                for (int ntl = 0; ntl < 8; ntl++) {
                    float p0 = __expf(sc[f][ntl][2 * half]     - mnew);
                    float p1 = __expf(sc[f][ntl][2 * half + 1] - mnew);
                    sc[f][ntl][2 * half] = p0; sc[f][ntl][2 * half + 1] = p1;
                    rs += p0 + p1;
                }
                rs += __shfl_xor_sync(0xffffffffu, rs, 1);
                rs += __shfl_xor_sync(0xffffffffu, rs, 2);
                lrow[f][half] += rs;
            }
        }

        // ---- P -> bf16 A-frags ----
        uint32_t pa[2][4][4];
#pragma unroll
        for (int f = 0; f < 2; f++)
#pragma unroll
            for (int kc = 0; kc < 4; kc++) {
                pa[f][kc][0] = pack_bf16x2(sc[f][2 * kc][0],     sc[f][2 * kc][1]);
                pa[f][kc][1] = pack_bf16x2(sc[f][2 * kc][2],     sc[f][2 * kc][3]);
                pa[f][kc][2] = pack_bf16x2(sc[f][2 * kc + 1][0], sc[f][2 * kc + 1][1]);
                pa[f][kc][3] = pack_bf16x2(sc[f][2 * kc + 1][2], sc[f][2 * kc + 1][3]);
            }

        // ---- ctx += P @ V ----
#pragma unroll
        for (int kc = 0; kc < 4; kc++) {
#pragma unroll
            for (int vt = 0; vt < 2; vt++) {
                int krow = kc * 16 + (grp & 1) * 8 + lr;
                int hdo  = vt * 16 + (grp >> 1) * 8;
                uint32_t vb[4];
                LDSM_X4_T(vb, sV + krow * KROWB + hdo * 2);
#pragma unroll
                for (int f = 0; f < 2; f++) {
                    MMA_BF16(o[f][2 * vt],     pa[f][kc], vb[0], vb[1]);
                    MMA_BF16(o[f][2 * vt + 1], pa[f][kc], vb[2], vb[3]);
                }
            }
        }
    }

    // ---- write partials ----
    const size_t pbase = ((size_t)(b * Hh + h) * MAX_SPLITS + s);
#pragma unroll
    for (int f = 0; f < 2; f++)
#pragma unroll
        for (int half = 0; half < 2; half++) {
            int row = wm + 16 * f + 8 * half + (lane >> 2);
            if (row < NQn) {
                if ((lane & 3) == 0) {
                    g_m_part[pbase * NQMAX + row] = mrow[f][half];
                    g_l_part[pbase * NQMAX + row] = lrow[f][half];
                }
#pragma unroll
                for (int j = 0; j < 4; j++) {
                    int d = j * 8 + 2 * (lane & 3);
                    *(float2*)(g_ctx_part + (pbase * NQMAX + row) * HD + d) =
                        make_float2(o[f][j][2 * half], o[f][j][2 * half + 1]);
                }
            }
        }
}

// ================= combine split partials (warp per (b,h,q)) ==============
__global__ __launch_bounds__(256)
void attn_combine(const int* __restrict__ offs, int Bn, int NQn)
{
    const int gwarp = (blockIdx.x * blockDim.x + threadIdx.x) >> 5;
    const int lane  = threadIdx.x & 31;
    const int tot = Bn * Hh * NQn;
    if (gwarp >= tot) return;
    const int q  = gwarp % NQn;
    const int bh = gwarp / NQn;
    const int b  = bh / Hh, h = bh % Hh;

    const int len = offs[b + 1] - offs[b];
    int ns = (len > 0) ? min((len + SPLIT_LEN - 1) / SPLIT_LEN, MAX_SPLITS) : 0;

    const size_t base = (size_t)bh * MAX_SPLITS;
    float M = -1e30f;
    for (int s2 = lane; s2 < ns; s2 += 32)
        M = fmaxf(M, g_m_part[(base + s2) * NQMAX + q]);
#pragma unroll
    for (int od = 16; od; od >>= 1) M = fmaxf(M, __shfl_xor_sync(0xffffffffu, M, od));

    float L = 0.f;
    for (int s2 = lane; s2 < ns; s2 += 32)
        L += __expf(g_m_part[(base + s2) * NQMAX + q] - M) * g_l_part[(base + s2) * NQMAX + q];
#pragma unroll
    for (int od = 16; od; od >>= 1) L += __shfl_xor_sync(0xffffffffu, L, od);

    float ctx = 0.f;
    for (int s2 = 0; s2 < ns; s2++) {
        float w = __expf(g_m_part[(base + s2) * NQMAX + q] - M);
        ctx += w * g_ctx_part[((base + s2) * NQMAX + q) * HD + lane];
    }
    float inv = (ns > 0 && L > 0.f) ? 1.f / L : 0.f;
    g_ctx[((size_t)b * NQn + q) * Dm + h * HD + lane] = ctx * inv;
}

// ================= launch =================
extern "C" void kernel_launch(void* const* d_in, const int* in_sizes, int n_in,
                              void* d_out, int out_size)
{
    const float* source = (const float*)d_in[0];
    const float* query  = (const float*)d_in[1];
    const int*   offs   = (const int*)  d_in[2];
    const float* Wq = (const float*)d_in[3];  const float* bq = (const float*)d_in[4];
    const float* Wk = (const float*)d_in[5];  const float* bk = (const float*)d_in[6];
    const float* Wv = (const float*)d_in[7];  const float* bv = (const float*)d_in[8];
    const float* Wo = (const float*)d_in[9];  const float* bo = (const float*)d_in[10];
    float* out = (float*)d_out;

    const int total = in_sizes[0] / Dm;
    const int Bn    = in_sizes[2] - 1;
    const int NQn   = in_sizes[1] / (Bn * Dm);
    const int Mq    = Bn * NQn;
    const float scale = rsqrtf((float)HD);

    void *pK, *pV, *pQ, *pC;
    cudaGetSymbolAddress(&pK, g_Kb);
    cudaGetSymbolAddress(&pV, g_Vb);
    cudaGetSymbolAddress(&pQ, g_Qb);
    cudaGetSymbolAddress(&pC, g_ctx);

    cudaFuncSetAttribute(kv_proj_mma, cudaFuncAttributeMaxDynamicSharedMemorySize,
                         KVSM_TOTAL);

    // 0) pre-swizzle weights + source to bf16 swizzled layouts
    w_prep<<<64, 256>>>(Wk, Wv);
    src_prep<<<(total * 32 + 255) / 256, 256>>>(source, total);

    // 1) Q projection -> bf16 (scale folded in)
    {
        dim3 grid((Mq + BM - 1) / BM, Dm / BN);
        sgemm_tn<<<grid, 256>>>(query, Wq, bq, nullptr, pQ, Mq, Dm, Dm, scale, 1);
    }
    // 2+3) K & V projections via bf16 HMMA (cp.async staged, pipelined)
    {
        dim3 grid((total + 127) / 128, 2);
        kv_proj_mma<<<grid, 256, KVSM_TOTAL>>>(bk, bv,
                                               (__nv_bfloat16*)pK, (__nv_bfloat16*)pV, total);
    }
    // 4) attention partials (HMMA flash attention)
    {
        int nsplit = (total + SPLIT_LEN - 1) / SPLIT_LEN;
        if (nsplit < 1) nsplit = 1;
        if (nsplit > MAX_SPLITS) nsplit = MAX_SPLITS;
        dim3 grid(nsplit, Hh, Bn);
        attn_partial<<<grid, 128>>>(offs, Bn, NQn);
    }
    // 5) combine
    {
        int tot = Bn * Hh * NQn;
        int blocks = (tot * 32 + 255) / 256;
        attn_combine<<<blocks, 256>>>(offs, Bn, NQn);
    }
    // 6) output projection + bias + residual (fp32)
    {
        dim3 grid((Mq + BM - 1) / BM, Dm / BN);
        sgemm_tn<<<grid, 256>>>((const float*)pC, Wo, bo, query, out, Mq, Dm, Dm, 1.0f, 0);
    }
}

// round 15
// speedup vs baseline: 6.0041x; 1.0125x over previous
#include <cuda_runtime.h>
#include <cuda_bf16.h>
#include <math.h>
#include <cstdint>

// ---------------- problem constants ----------------
#define Dm 256
#define Hh 8
#define HD 32
#define NQMAX 128
#define MAXB 16
#define MAX_TOTAL 65536
#define SPLIT_LEN 2048
#define MAX_SPLITS 32

// ---------------- device scratch ----------------
__device__ __nv_bfloat16 g_Kb[MAX_TOTAL * Dm];
__device__ __nv_bfloat16 g_Vb[MAX_TOTAL * Dm];
__device__ __nv_bfloat16 g_Qb[MAXB * NQMAX * Dm];
__device__ float g_ctx[MAXB * NQMAX * Dm];
__device__ float g_ctx_part[(size_t)MAXB * Hh * MAX_SPLITS * NQMAX * HD];
__device__ float g_m_part[(size_t)MAXB * Hh * MAX_SPLITS * NQMAX];
__device__ float g_l_part[(size_t)MAXB * Hh * MAX_SPLITS * NQMAX];
// pre-swizzled bf16 W for K/V proj: [matrix(2)][ntile(2)][kb(4)][row(128)][chunk(8)] x 16B
__device__ uint4 g_Wswz[2 * 2 * 4 * 128 * 8];
// pre-swizzled bf16 source: [kb(4)][token(MAX_TOTAL)][chunk(8)] x 16B  (32 MB)
__device__ uint4 g_Sswz[(size_t)4 * MAX_TOTAL * 8];

// ================= helpers =================
__device__ __forceinline__ uint32_t smem_to_u32(const void* p) {
    uint32_t a;
    asm("{ .reg .u64 t; cvta.to.shared.u64 t, %1; cvt.u32.u64 %0, t; }" : "=r"(a) : "l"(p));
    return a;
}
#define SMEM_SWZ(off) ((off) ^ (((off) >> 3) & 0x70))

__device__ __forceinline__ uint32_t pack_bf16x2(float a, float b) {
    uint32_t r;
    asm("cvt.rn.bf16x2.f32 %0, %1, %2;" : "=r"(r) : "f"(b), "f"(a));
    return r;
}

#define CP_ASYNC16(dst, src) \
    asm volatile("cp.async.cg.shared.global [%0], [%1], 16;" :: "r"(dst), "l"(src))
#define CP_ASYNC16_P(dst, src, sz) \
    asm volatile("cp.async.cg.shared.global [%0], [%1], 16, %2;" :: "r"(dst), "l"(src), "r"(sz))
#define CP_COMMIT() asm volatile("cp.async.commit_group;" ::: "memory")
#define CP_WAIT(n)  asm volatile("cp.async.wait_group %0;" :: "n"(n) : "memory")

// ldmatrix x4 (row-major 8x8 b16 tiles)
#define LDSM_X4(r, addr) \
    asm volatile("ldmatrix.sync.aligned.m8n8.x4.shared.b16 {%0,%1,%2,%3}, [%4];" \
        : "=r"((r)[0]), "=r"((r)[1]), "=r"((r)[2]), "=r"((r)[3]) : "r"(addr))
#define LDSM_X4_T(r, addr) \
    asm volatile("ldmatrix.sync.aligned.m8n8.x4.trans.shared.b16 {%0,%1,%2,%3}, [%4];" \
        : "=r"((r)[0]), "=r"((r)[1]), "=r"((r)[2]), "=r"((r)[3]) : "r"(addr))

// HMMA bf16: D(16x8) += A(16x16,row) * B(16x8,col)
#define MMA_BF16(d, a, b0, b1) \
    asm volatile("mma.sync.aligned.m16n8k16.row.col.f32.bf16.bf16.f32 " \
        "{%0,%1,%2,%3}, {%4,%5,%6,%7}, {%8,%9}, {%0,%1,%2,%3};" \
        : "+f"((d)[0]), "+f"((d)[1]), "+f"((d)[2]), "+f"((d)[3]) \
        : "r"((a)[0]), "r"((a)[1]), "r"((a)[2]), "r"((a)[3]), "r"(b0), "r"(b1))

// ================= W pre-swizzle (fp32 -> bf16, SW128 chunk-permuted) ======
__global__ void __launch_bounds__(256)
w_prep(const float* __restrict__ Wk, const float* __restrict__ Wv)
{
    int idx = blockIdx.x * 256 + threadIdx.x;    // 0 .. 16383
    int c   = idx & 7;
    int row = (idx >> 3) & 127;
    int kb  = (idx >> 10) & 3;
    int nt  = (idx >> 12) & 1;
    int mi  = (idx >> 13) & 1;
    const float* W = mi ? Wv : Wk;
    const float* src = W + (size_t)(nt * 128 + row) * 256 + kb * 64 + c * 8;
    float4 a = *(const float4*)src;
    float4 b = *(const float4*)(src + 4);
    uint4 u = make_uint4(pack_bf16x2(a.x, a.y), pack_bf16x2(a.z, a.w),
                         pack_bf16x2(b.x, b.y), pack_bf16x2(b.z, b.w));
    g_Wswz[(((mi * 2 + nt) * 4 + kb) * 128 + row) * 8 + (c ^ (row & 7))] = u;
}

// ================= source pre-swizzle (fp32 -> bf16, chunk-permuted) =======
__global__ void __launch_bounds__(256)
src_prep(const float* __restrict__ S, int total)
{
    int idx = blockIdx.x * 256 + threadIdx.x;    // chunk id
    if (idx >= total * 32) return;
    int c     = idx & 7;
    int kb    = (idx >> 3) & 3;
    int token = idx >> 5;
    const float* src = S + (size_t)token * 256 + kb * 64 + c * 8;
    float4 a = *(const float4*)src;
    float4 b = *(const float4*)(src + 4);
    uint4 u = make_uint4(pack_bf16x2(a.x, a.y), pack_bf16x2(a.z, a.w),
                         pack_bf16x2(b.x, b.y), pack_bf16x2(b.z, b.w));
    g_Sswz[((size_t)kb * MAX_TOTAL + token) * 8 + (c ^ (token & 7))] = u;
}

// ================= bf16 HMMA K/V projection (512 thr, K/V warp split) ======
#define KVSM_A  0
#define KVSM_BK (4 * 128 * 128)
#define KVSM_BV (2 * 4 * 128 * 128)
#define KVSM_TOTAL (3 * 4 * 128 * 128)

__global__ void __launch_bounds__(512, 1)
kv_proj_mma(const float* __restrict__ bkp, const float* __restrict__ bvp,
            __nv_bfloat16* __restrict__ outK, __nv_bfloat16* __restrict__ outV, int M)
{
    extern __shared__ char smem[];
    const int tid = threadIdx.x;
    const int m0 = blockIdx.x * 128;
    const int nt = blockIdx.y;
    const int n0 = nt * 128;
    const uint32_t sbase = smem_to_u32(smem);

    // ---- W tiles (both matrices) via cp.async ----
    {
        const char* base = (const char*)g_Wswz;
#pragma unroll
        for (int i = 0; i < 8; i++) {
            int idx = tid + 512 * i;            // K matrix, 4096 chunks
            int kb = idx >> 10, row = (idx >> 3) & 127, c = idx & 7;
            uint32_t dst = sbase + KVSM_BK + kb * 16384 + row * 128 + c * 16;
            const char* src = base + ((((size_t)nt) * 4 + kb) * 1024 + row * 8 + c) * 16;
            CP_ASYNC16(dst, src);
        }
#pragma unroll
        for (int i = 0; i < 8; i++) {
            int idx = tid + 512 * i;            // V matrix
            int kb = idx >> 10, row = (idx >> 3) & 127, c = idx & 7;
            uint32_t dst = sbase + KVSM_BV + kb * 16384 + row * 128 + c * 16;
            const char* src = base + ((((size_t)(2 + nt)) * 4 + kb) * 1024 + row * 8 + c) * 16;
            CP_ASYNC16(dst, src);
        }
    }
    // A kb blocks via cp.async from pre-swizzled bf16 source (zero-fill OOB)
    auto issueA = [&](int kb) {
        const char* base = (const char*)g_Sswz;
#pragma unroll
        for (int i = 0; i < 2; i++) {
            int idx = tid + 512 * i;            // 1024 chunks
            int row = idx >> 3, c = idx & 7;
            int gm = m0 + row;
            int ok = gm < M;
            int rr = ok ? gm : 0;
            uint32_t dst = sbase + KVSM_A + kb * 16384 + row * 128 + c * 16;
            const char* src = base + (((size_t)kb * MAX_TOTAL + rr) * 8 + c) * 16;
            CP_ASYNC16_P(dst, src, ok ? 16 : 0);
        }
    };
    issueA(0); CP_COMMIT();
    issueA(1); CP_COMMIT();
    issueA(2); CP_COMMIT();
    issueA(3); CP_COMMIT();

    const int lane = tid & 31;
    const int wid  = tid >> 5;
    const int mat  = wid >> 3;          // 0 = K, 1 = V
    const int gw   = wid & 7;
    const int wm = (gw & 3) * 32;
    const int wn = (gw >> 2) * 64;
    const uint32_t bBase0 = sbase + (mat ? KVSM_BV : KVSM_BK);

    float acc[2][8][4];
#pragma unroll
    for (int f = 0; f < 2; f++)
#pragma unroll
        for (int g = 0; g < 8; g++)
#pragma unroll
            for (int c = 0; c < 4; c++) acc[f][g][c] = 0.f;

    const int a_row    = wm + (lane & 15);
    const int a_kchunk = (lane >> 4) * 8;
    const int b_row    = wn + ((lane >> 4) & 1) * 8 + (lane & 7);
    const int b_kchunk = ((lane >> 3) & 1) * 8;

    auto compute_kb = [&](int kb) {
        const uint32_t aBase = sbase + KVSM_A + kb * 16384;
        const uint32_t bBase = bBase0 + kb * 16384;
#pragma unroll
        for (int ks = 0; ks < 4; ks++) {
            const int kk = ks * 16;
            uint32_t a0r[4], a1r[4];
            {
                uint32_t off0 = (uint32_t)( a_row       * 128 + (kk + a_kchunk) * 2);
                uint32_t off1 = (uint32_t)((a_row + 16) * 128 + (kk + a_kchunk) * 2);
                LDSM_X4(a0r, aBase + SMEM_SWZ(off0));
                LDSM_X4(a1r, aBase + SMEM_SWZ(off1));
            }
            uint32_t bf[4][4];
#pragma unroll
            for (int p = 0; p < 4; p++) {
                uint32_t off = (uint32_t)((b_row + p * 16) * 128 + (kk + b_kchunk) * 2);
                LDSM_X4(bf[p], bBase + SMEM_SWZ(off));
            }
#pragma unroll
            for (int p = 0; p < 4; p++) {
                MMA_BF16(acc[0][2 * p],     a0r, bf[p][0], bf[p][1]);
                MMA_BF16(acc[0][2 * p + 1], a0r, bf[p][2], bf[p][3]);
                MMA_BF16(acc[1][2 * p],     a1r, bf[p][0], bf[p][1]);
                MMA_BF16(acc[1][2 * p + 1], a1r, bf[p][2], bf[p][3]);
            }
        }
    };

    // staircase: W+A0 ready -> compute kb0 while A1..A3 land
    CP_WAIT(3); __syncthreads(); compute_kb(0);
    CP_WAIT(2); __syncthreads(); compute_kb(1);
    CP_WAIT(1); __syncthreads(); compute_kb(2);
    CP_WAIT(0); __syncthreads(); compute_kb(3);

    // ---- epilogue: bias + bf16 store (each warp stores its matrix) ----
    const float* bias = mat ? bvp : bkp;
    __nv_bfloat16* outp = mat ? outV : outK;
#pragma unroll
    for (int f = 0; f < 2; f++) {
        const int mA = m0 + wm + f * 16 + (lane >> 2);
        const int mB = mA + 8;
#pragma unroll
        for (int g = 0; g < 8; g++) {
            const int n = n0 + wn + g * 8 + (lane & 3) * 2;
            const float b0 = bias[n], b1 = bias[n + 1];
            if (mA < M)
                *(uint32_t*)(outp + (size_t)mA * 256 + n) =
                    pack_bf16x2(acc[f][g][0] + b0, acc[f][g][1] + b1);
            if (mB < M)
                *(uint32_t*)(outp + (size_t)mB * 256 + n) =
                    pack_bf16x2(acc[f][g][2] + b0, acc[f][g][3] + b1);
        }
    }
}

// ================= fp32 SGEMM (Q-proj -> bf16 out, out-proj -> fp32) =======
#define BM 128
#define BN 64
#define BK 32
__global__ __launch_bounds__(256)
void sgemm_tn(const float* __restrict__ A, const float* __restrict__ W,
              const float* __restrict__ bias, const float* __restrict__ resid,
              void* __restrict__ outv, int M, int N, int K, float alpha, int obf)
{
    __shared__ float As[BK][BM + 4];
    __shared__ float Ws[BK][BN + 4];
    const int t = threadIdx.x, tx = t & 15, ty = t >> 4;
    const int m0 = blockIdx.x * BM, n0 = blockIdx.y * BN;
    float acc[8][4];
#pragma unroll
    for (int i = 0; i < 8; i++)
#pragma unroll
        for (int j = 0; j < 4; j++) acc[i][j] = 0.f;
    const int ar = t >> 3, ac = (t & 7) * 4;
    for (int k0 = 0; k0 < K; k0 += BK) {
#pragma unroll
        for (int i = 0; i < 4; i++) {
            int row = ar + 32 * i, gm = m0 + row;
            float4 v = make_float4(0.f, 0.f, 0.f, 0.f);
            if (gm < M) v = *(const float4*)(A + (size_t)gm * K + k0 + ac);
            As[ac + 0][row] = v.x; As[ac + 1][row] = v.y;
            As[ac + 2][row] = v.z; As[ac + 3][row] = v.w;
        }
#pragma unroll
        for (int i = 0; i < 2; i++) {
            int n = ar + 32 * i;
            float4 v = *(const float4*)(W + (size_t)(n0 + n) * K + k0 + ac);
            Ws[ac + 0][n] = v.x; Ws[ac + 1][n] = v.y;
            Ws[ac + 2][n] = v.z; Ws[ac + 3][n] = v.w;
        }
        __syncthreads();
#pragma unroll
        for (int kk = 0; kk < BK; kk++) {
            float a[8], w[4];
#pragma unroll
            for (int i = 0; i < 8; i++) a[i] = As[kk][ty * 8 + i];
#pragma unroll
            for (int j = 0; j < 4; j++) w[j] = Ws[kk][tx * 4 + j];
#pragma unroll
            for (int i = 0; i < 8; i++)
#pragma unroll
                for (int j = 0; j < 4; j++) acc[i][j] = fmaf(a[i], w[j], acc[i][j]);
        }
        __syncthreads();
    }
#pragma unroll
    for (int i = 0; i < 8; i++) {
        int gm = m0 + ty * 8 + i;
        if (gm >= M) continue;
#pragma unroll
        for (int j = 0; j < 4; j++) {
            int gn = n0 + tx * 4 + j;
            float v = acc[i][j];
            if (bias) v += bias[gn];
            v *= alpha;
            if (resid) v += resid[(size_t)gm * N + gn];
            if (obf) ((__nv_bfloat16*)outv)[(size_t)gm * N + gn] = __float2bfloat16(v);
            else     ((float*)outv)[(size_t)gm * N + gn] = v;
        }
    }
}

// ================= HMMA flash-attention partials (cp.async pipelined) ======
#define TK 64
#define KROWB 80       /* smem row stride bytes: conflict-free ldmatrix */
#define STG_B 10240    /* per-stage bytes: K(64*80) + V(64*80) */
#define NSTG 3

__global__ void __launch_bounds__(128, 2)
attn_partial(const int* __restrict__ offs, int Bn, int NQn)
{
    const int s = blockIdx.x, h = blockIdx.y, b = blockIdx.z;
    const int tid = threadIdx.x;
    const int lane = tid & 31, wid = tid >> 5;
    const int beg = offs[b];
    const int len = offs[b + 1] - beg;
    const int k0  = s * SPLIT_LEN;
    if (k0 >= len) return;
    const int kend = min(k0 + SPLIT_LEN, len);

    __shared__ __align__(16) char sAll[NSTG * STG_B];
    const uint32_t sbase = smem_to_u32(sAll);

    const int wm = wid * 32;

    // ---- Q fragments from bf16 g_Qb (scale folded at projection) ----
    uint32_t qa[2][2][4];
#pragma unroll
    for (int f = 0; f < 2; f++)
#pragma unroll
        for (int c = 0; c < 2; c++) {
            const int col = h * HD + c * 16 + 2 * (lane & 3);
#pragma unroll
            for (int e = 0; e < 4; e++) {
                int row = wm + 16 * f + (lane >> 2) + (e & 1) * 8;
                int cc  = col + (e >> 1) * 8;
                qa[f][c][e] = (row < NQn)
                    ? *(const uint32_t*)(g_Qb + ((size_t)(b * NQn + row)) * Dm + cc) : 0u;
            }
        }

    float o[2][4][4];
#pragma unroll
    for (int f = 0; f < 2; f++)
#pragma unroll
        for (int j = 0; j < 4; j++)
#pragma unroll
            for (int e = 0; e < 4; e++) o[f][j][e] = 0.f;
    float mrow[2][2], lrow[2][2];
#pragma unroll
    for (int f = 0; f < 2; f++) { mrow[f][0] = mrow[f][1] = -1e30f; lrow[f][0] = lrow[f][1] = 0.f; }

    const int grp = lane >> 3, lr = lane & 7;
    const int nch = (kend - k0 + TK - 1) / TK;

    auto issue = [&](int ci) {
        const int buf = ci % NSTG;
        const int ktl = k0 + ci * TK;
        const int nv2 = min(TK, kend - ktl);
        const uint32_t sK = sbase + buf * STG_B;
        const uint32_t sV = sK + 5120;
#pragma unroll
        for (int i = 0; i < 2; i++) {
            int idx = tid + 128 * i;
            int row = idx >> 2, c = idx & 3;
            int ok = row < nv2;
            int rr = ok ? row : 0;
            const char* srcK = (const char*)(g_Kb + ((size_t)(beg + ktl + rr)) * Dm + h * HD) + c * 16;
            const char* srcV = (const char*)(g_Vb + ((size_t)(beg + ktl + rr)) * Dm + h * HD) + c * 16;
            int sz = ok ? 16 : 0;
            CP_ASYNC16_P(sK + row * KROWB + c * 16, srcK, sz);
            CP_ASYNC16_P(sV + row * KROWB + c * 16, srcV, sz);
        }
        CP_COMMIT();
    };

    issue(0);
    if (nch > 1) issue(1);
    for (int ci = 0; ci < nch; ci++) {
        if (ci + 2 < nch) { issue(ci + 2); CP_WAIT(2); }
        else if (ci + 1 < nch) CP_WAIT(1);
        else CP_WAIT(0);
        __syncthreads();

        const int buf = ci % NSTG;
        const uint32_t sK = sbase + buf * STG_B;
        const uint32_t sV = sK + 5120;
        const int nv = min(TK, kend - (k0 + ci * TK));

        // ---- S = Q @ K^T ----
        float sc[2][8][4];
#pragma unroll
        for (int f = 0; f < 2; f++)
#pragma unroll
            for (int ntl = 0; ntl < 8; ntl++)
#pragma unroll
                for (int e = 0; e < 4; e++) sc[f][ntl][e] = 0.f;

#pragma unroll
        for (int c = 0; c < 2; c++) {
#pragma unroll
            for (int p = 0; p < 4; p++) {
                int krow = p * 16 + (grp >> 1) * 8 + lr;
                int hdo  = c * 16 + (grp & 1) * 8;
                uint32_t kb[4];
                LDSM_X4(kb, sK + krow * KROWB + hdo * 2);
#pragma unroll
                for (int f = 0; f < 2; f++) {
                    MMA_BF16(sc[f][2 * p],     qa[f][c], kb[0], kb[1]);
                    MMA_BF16(sc[f][2 * p + 1], qa[f][c], kb[2], kb[3]);
                }
            }
        }

        if (nv < TK) {
#pragma unroll
            for (int ntl = 0; ntl < 8; ntl++) {
                int c0 = ntl * 8 + 2 * (lane & 3);
#pragma unroll
                for (int f = 0; f < 2; f++) {
                    if (c0     >= nv) { sc[f][ntl][0] = -3e30f; sc[f][ntl][2] = -3e30f; }
                    if (c0 + 1 >= nv) { sc[f][ntl][1] = -3e30f; sc[f][ntl][3] = -3e30f; }
                }
            }
        }

        // ---- online softmax ----
#pragma unroll
        for (int f = 0; f < 2; f++) {
#pragma unroll
            for (int half = 0; half < 2; half++) {
                float mx = -3e30f;
#pragma unroll
                for (int ntl = 0; ntl < 8; ntl++)
                    mx = fmaxf(mx, fmaxf(sc[f][ntl][2 * half], sc[f][ntl][2 * half + 1]));
                mx = fmaxf(mx, __shfl_xor_sync(0xffffffffu, mx, 1));
                mx = fmaxf(mx, __shfl_xor_sync(0xffffffffu, mx, 2));
                float mnew = fmaxf(mrow[f][half], mx);
                float corr = __expf(mrow[f][half] - mnew);
                mrow[f][half] = mnew;
                lrow[f][half] *= corr;
#pragma unroll
                for (int j = 0; j < 4; j++) {
                    o[f][j][2 * half]     *= corr;
                    o[f][j][2 * half + 1] *= corr;
                }
                float rs = 0.f;
#pragma unroll
                for (int ntl = 0; ntl < 8; ntl++) {
                    float p0 = __expf(sc[f][ntl][2 * half]     - mnew);
                    float p1 = __expf(sc[f][ntl][2 * half + 1] - mnew);
                    sc[f][ntl][2 * half] = p0; sc[f][ntl][2 * half + 1] = p1;
                    rs += p0 + p1;
                }
                rs += __shfl_xor_sync(0xffffffffu, rs, 1);
                rs += __shfl_xor_sync(0xffffffffu, rs, 2);
                lrow[f][half] += rs;
            }
        }

        // ---- P -> bf16 A-frags ----
        uint32_t pa[2][4][4];
#pragma unroll
        for (int f = 0; f < 2; f++)
#pragma unroll
            for (int kc = 0; kc < 4; kc++) {
                pa[f][kc][0] = pack_bf16x2(sc[f][2 * kc][0],     sc[f][2 * kc][1]);
                pa[f][kc][1] = pack_bf16x2(sc[f][2 * kc][2],     sc[f][2 * kc][3]);
                pa[f][kc][2] = pack_bf16x2(sc[f][2 * kc + 1][0], sc[f][2 * kc + 1][1]);
                pa[f][kc][3] = pack_bf16x2(sc[f][2 * kc + 1][2], sc[f][2 * kc + 1][3]);
            }

        // ---- ctx += P @ V ----
#pragma unroll
        for (int kc = 0; kc < 4; kc++) {
#pragma unroll
            for (int vt = 0; vt < 2; vt++) {
                int krow = kc * 16 + (grp & 1) * 8 + lr;
                int hdo  = vt * 16 + (grp >> 1) * 8;
                uint32_t vb[4];
                LDSM_X4_T(vb, sV + krow * KROWB + hdo * 2);
#pragma unroll
                for (int f = 0; f < 2; f++) {
                    MMA_BF16(o[f][2 * vt],     pa[f][kc], vb[0], vb[1]);
                    MMA_BF16(o[f][2 * vt + 1], pa[f][kc], vb[2], vb[3]);
                }
            }
        }
    }

    // ---- write partials ----
    const size_t pbase = ((size_t)(b * Hh + h) * MAX_SPLITS + s);
#pragma unroll
    for (int f = 0; f < 2; f++)
#pragma unroll
        for (int half = 0; half < 2; half++) {
            int row = wm + 16 * f + 8 * half + (lane >> 2);
            if (row < NQn) {
                if ((lane & 3) == 0) {
                    g_m_part[pbase * NQMAX + row] = mrow[f][half];
                    g_l_part[pbase * NQMAX + row] = lrow[f][half];
                }
#pragma unroll
                for (int j = 0; j < 4; j++) {
                    int d = j * 8 + 2 * (lane & 3);
                    *(float2*)(g_ctx_part + (pbase * NQMAX + row) * HD + d) =
                        make_float2(o[f][j][2 * half], o[f][j][2 * half + 1]);
                }
            }
        }
}

// ================= combine split partials (warp per (b,h,q)) ==============
__global__ __launch_bounds__(256)
void attn_combine(const int* __restrict__ offs, int Bn, int NQn)
{
    const int gwarp = (blockIdx.x * blockDim.x + threadIdx.x) >> 5;
    const int lane  = threadIdx.x & 31;
    const int tot = Bn * Hh * NQn;
    if (gwarp >= tot) return;
    const int q  = gwarp % NQn;
    const int bh = gwarp / NQn;
    const int b  = bh / Hh, h = bh % Hh;

    const int len = offs[b + 1] - offs[b];
    int ns = (len > 0) ? min((len + SPLIT_LEN - 1) / SPLIT_LEN, MAX_SPLITS) : 0;

    const size_t base = (size_t)bh * MAX_SPLITS;
    float M = -1e30f;
    for (int s2 = lane; s2 < ns; s2 += 32)
        M = fmaxf(M, g_m_part[(base + s2) * NQMAX + q]);
#pragma unroll
    for (int od = 16; od; od >>= 1) M = fmaxf(M, __shfl_xor_sync(0xffffffffu, M, od));

    float L = 0.f;
    for (int s2 = lane; s2 < ns; s2 += 32)
        L += __expf(g_m_part[(base + s2) * NQMAX + q] - M) * g_l_part[(base + s2) * NQMAX + q];
#pragma unroll
    for (int od = 16; od; od >>= 1) L += __shfl_xor_sync(0xffffffffu, L, od);

    float ctx = 0.f;
    for (int s2 = 0; s2 < ns; s2++) {
        float w = __expf(g_m_part[(base + s2) * NQMAX + q] - M);
        ctx += w * g_ctx_part[((base + s2) * NQMAX + q) * HD + lane];
    }
    float inv = (ns > 0 && L > 0.f) ? 1.f / L : 0.f;
    g_ctx[((size_t)b * NQn + q) * Dm + h * HD + lane] = ctx * inv;
}

// ================= launch =================
extern "C" void kernel_launch(void* const* d_in, const int* in_sizes, int n_in,
                              void* d_out, int out_size)
{
    const float* source = (const float*)d_in[0];
    const float* query  = (const float*)d_in[1];
    const int*   offs   = (const int*)  d_in[2];
    const float* Wq = (const float*)d_in[3];  const float* bq = (const float*)d_in[4];
    const float* Wk = (const float*)d_in[5];  const float* bk = (const float*)d_in[6];
    const float* Wv = (const float*)d_in[7];  const float* bv = (const float*)d_in[8];
    const float* Wo = (const float*)d_in[9];  const float* bo = (const float*)d_in[10];
    float* out = (float*)d_out;

    const int total = in_sizes[0] / Dm;
    const int Bn    = in_sizes[2] - 1;
    const int NQn   = in_sizes[1] / (Bn * Dm);
    const int Mq    = Bn * NQn;
    const float scale = rsqrtf((float)HD);

    void *pK, *pV, *pQ, *pC;
    cudaGetSymbolAddress(&pK, g_Kb);
    cudaGetSymbolAddress(&pV, g_Vb);
    cudaGetSymbolAddress(&pQ, g_Qb);
    cudaGetSymbolAddress(&pC, g_ctx);

    cudaFuncSetAttribute(kv_proj_mma, cudaFuncAttributeMaxDynamicSharedMemorySize,
                         KVSM_TOTAL);

    // 0) pre-swizzle weights + source to bf16 swizzled layouts
    w_prep<<<64, 256>>>(Wk, Wv);
    src_prep<<<(total * 32 + 255) / 256, 256>>>(source, total);

    // 1) Q projection -> bf16 (scale folded in)
    {
        dim3 grid((Mq + BM - 1) / BM, Dm / BN);
        sgemm_tn<<<grid, 256>>>(query, Wq, bq, nullptr, pQ, Mq, Dm, Dm, scale, 1);
    }
    // 2+3) K & V projections via bf16 HMMA (512 thr, K/V warp split)
    {
        dim3 grid((total + 127) / 128, 2);
        kv_proj_mma<<<grid, 512, KVSM_TOTAL>>>(bk, bv,
                                               (__nv_bfloat16*)pK, (__nv_bfloat16*)pV, total);
    }
    // 4) attention partials (HMMA flash attention)
    {
        int nsplit = (total + SPLIT_LEN - 1) / SPLIT_LEN;
        if (nsplit < 1) nsplit = 1;
        if (nsplit > MAX_SPLITS) nsplit = MAX_SPLITS;
        dim3 grid(nsplit, Hh, Bn);
        attn_partial<<<grid, 128>>>(offs, Bn, NQn);
    }
    // 5) combine
    {
        int tot = Bn * Hh * NQn;
        int blocks = (tot * 32 + 255) / 256;
        attn_combine<<<blocks, 256>>>(offs, Bn, NQn);
    }
    // 6) output projection + bias + residual (fp32)
    {
        dim3 grid((Mq + BM - 1) / BM, Dm / BN);
        sgemm_tn<<<grid, 256>>>((const float*)pC, Wo, bo, query, out, Mq, Dm, Dm, 1.0f, 0);
    }
}